// round 8
// baseline (speedup 1.0000x reference)
#include <cuda_runtime.h>
#include <cuda_bf16.h>
#include <math.h>
#include <stdint.h>

#define D_MODEL 2048
#define N_HEADS 16
#define HEAD_DIM 128
#define MLP_DIM 8192
#define BATCH 2
#define SEQ 2048
#define TOK (BATCH * SEQ)

typedef __nv_bfloat16 bf16;

// ---------------- scratch (static device globals) ---------------------------
__device__ bf16 g_h_hi[(size_t)TOK * D_MODEL],  g_h_lo[(size_t)TOK * D_MODEL];
__device__ bf16 g_q_hi[(size_t)TOK * D_MODEL],  g_q_lo[(size_t)TOK * D_MODEL];
__device__ bf16 g_k_hi[(size_t)TOK * D_MODEL],  g_k_lo[(size_t)TOK * D_MODEL];
__device__ bf16 g_v_hi[(size_t)TOK * D_MODEL],  g_v_lo[(size_t)TOK * D_MODEL];
__device__ bf16 g_att_hi[(size_t)TOK * D_MODEL], g_att_lo[(size_t)TOK * D_MODEL];
__device__ bf16 g_up_hi[(size_t)TOK * MLP_DIM], g_up_lo[(size_t)TOK * MLP_DIM];
__device__ bf16 g_wq_hi[(size_t)D_MODEL * D_MODEL], g_wq_lo[(size_t)D_MODEL * D_MODEL];
__device__ bf16 g_wk_hi[(size_t)D_MODEL * D_MODEL], g_wk_lo[(size_t)D_MODEL * D_MODEL];
__device__ bf16 g_wv_hi[(size_t)D_MODEL * D_MODEL], g_wv_lo[(size_t)D_MODEL * D_MODEL];
__device__ bf16 g_wo_hi[(size_t)D_MODEL * D_MODEL], g_wo_lo[(size_t)D_MODEL * D_MODEL];
__device__ bf16 g_wu_hi[(size_t)MLP_DIM * D_MODEL], g_wu_lo[(size_t)MLP_DIM * D_MODEL];
__device__ bf16 g_wd_hi[(size_t)D_MODEL * MLP_DIM], g_wd_lo[(size_t)D_MODEL * MLP_DIM];
__device__ float g_x1[(size_t)TOK * D_MODEL];

// ================= PTX helpers (baseline PTX, sm_80+) =======================
__device__ __forceinline__ uint32_t smem_to_u32(const void* p) {
    uint32_t a;
    asm("{ .reg .u64 t; cvta.to.shared.u64 t, %1; cvt.u32.u64 %0, t; }"
        : "=r"(a) : "l"(p));
    return a;
}
__device__ __forceinline__ void ldsm_x4(uint32_t addr, uint32_t* r) {
    asm volatile("ldmatrix.sync.aligned.m8n8.x4.shared.b16 {%0,%1,%2,%3}, [%4];"
                 : "=r"(r[0]), "=r"(r[1]), "=r"(r[2]), "=r"(r[3]) : "r"(addr));
}
__device__ __forceinline__ void mma_bf16(float* d, const uint32_t* a,
                                         const uint32_t* b) {
    asm volatile(
        "mma.sync.aligned.m16n8k16.row.col.f32.bf16.bf16.f32 "
        "{%0,%1,%2,%3}, {%4,%5,%6,%7}, {%8,%9}, {%0,%1,%2,%3};"
        : "+f"(d[0]), "+f"(d[1]), "+f"(d[2]), "+f"(d[3])
        : "r"(a[0]), "r"(a[1]), "r"(a[2]), "r"(a[3]), "r"(b[0]), "r"(b[1]));
}
__device__ __forceinline__ uint32_t bf2_bits(__nv_bfloat162 v) {
    return *reinterpret_cast<uint32_t*>(&v);
}
#define CP16(dst, src) \
    asm volatile("cp.async.cg.shared.global [%0], [%1], 16;" \
                 :: "r"(dst), "l"(src) : "memory")
#define CPCOMMIT() asm volatile("cp.async.commit_group;" ::: "memory")
#define CPWAIT(n)  asm volatile("cp.async.wait_group %0;" :: "n"(n) : "memory")

// ================= fp32 -> bf16 hi/lo split (weights; 2 launches) ===========
__device__ __forceinline__ void split_store(const float* src, bf16* hi, bf16* lo,
                                            int i) {
    float4 v = reinterpret_cast<const float4*>(src)[i];
    __nv_bfloat162 h01 = __floats2bfloat162_rn(v.x, v.y);
    __nv_bfloat162 h23 = __floats2bfloat162_rn(v.z, v.w);
    __nv_bfloat162 l01 = __floats2bfloat162_rn(v.x - __bfloat162float(h01.x),
                                               v.y - __bfloat162float(h01.y));
    __nv_bfloat162 l23 = __floats2bfloat162_rn(v.z - __bfloat162float(h23.x),
                                               v.w - __bfloat162float(h23.y));
    reinterpret_cast<uint2*>(hi)[i] = make_uint2(bf2_bits(h01), bf2_bits(h23));
    reinterpret_cast<uint2*>(lo)[i] = make_uint2(bf2_bits(l01), bf2_bits(l23));
}

__global__ void split_dd(const float* __restrict__ wq, const float* __restrict__ wk,
                         const float* __restrict__ wv, const float* __restrict__ wo,
                         bf16* qh, bf16* ql, bf16* kh, bf16* kl,
                         bf16* vh, bf16* vl, bf16* oh, bf16* ol) {
    int i = blockIdx.x * blockDim.x + threadIdx.x;
    if (i >= D_MODEL * D_MODEL / 4) return;
    switch (blockIdx.y) {
        case 0: split_store(wq, qh, ql, i); break;
        case 1: split_store(wk, kh, kl, i); break;
        case 2: split_store(wv, vh, vl, i); break;
        default: split_store(wo, oh, ol, i); break;
    }
}
__global__ void split_ud(const float* __restrict__ wu, const float* __restrict__ wd,
                         bf16* uh, bf16* ul, bf16* dh, bf16* dl) {
    int i = blockIdx.x * blockDim.x + threadIdx.x;
    if (i >= MLP_DIM * D_MODEL / 4) return;
    if (blockIdx.y == 0) split_store(wu, uh, ul, i);
    else                 split_store(wd, dh, dl, i);
}

// ================= RMSNorm -> bf16 hi/lo =====================================
__global__ void rmsnorm_split(const float* __restrict__ x,
                              const float* __restrict__ w,
                              bf16* __restrict__ hi, bf16* __restrict__ lo) {
    int row = blockIdx.x;
    const float4* xr = reinterpret_cast<const float4*>(x + (size_t)row * D_MODEL);
    const float4* w4 = reinterpret_cast<const float4*>(w);

    float ss = 0.f;
    for (int i = threadIdx.x; i < D_MODEL / 4; i += blockDim.x) {
        float4 v = xr[i];
        ss += v.x * v.x + v.y * v.y + v.z * v.z + v.w * v.w;
    }
    for (int off = 16; off > 0; off >>= 1)
        ss += __shfl_xor_sync(0xFFFFFFFFu, ss, off);
    __shared__ float red[8];
    __shared__ float s_rms;
    int lane = threadIdx.x & 31, wid = threadIdx.x >> 5;
    if (lane == 0) red[wid] = ss;
    __syncthreads();
    if (threadIdx.x == 0) {
        float tt = 0.f;
        #pragma unroll
        for (int i = 0; i < 8; i++) tt += red[i];
        s_rms = rsqrtf(tt / (float)D_MODEL + 1e-6f);
    }
    __syncthreads();
    float r = s_rms;
    uint2* h2 = reinterpret_cast<uint2*>(hi + (size_t)row * D_MODEL);
    uint2* l2 = reinterpret_cast<uint2*>(lo + (size_t)row * D_MODEL);
    for (int i = threadIdx.x; i < D_MODEL / 4; i += blockDim.x) {
        float4 v = xr[i];
        float4 ww = w4[i];
        float y0 = v.x * r * ww.x, y1 = v.y * r * ww.y;
        float y2 = v.z * r * ww.z, y3 = v.w * r * ww.w;
        __nv_bfloat162 h01 = __floats2bfloat162_rn(y0, y1);
        __nv_bfloat162 h23 = __floats2bfloat162_rn(y2, y3);
        __nv_bfloat162 l01 = __floats2bfloat162_rn(y0 - __bfloat162float(h01.x),
                                                   y1 - __bfloat162float(h01.y));
        __nv_bfloat162 l23 = __floats2bfloat162_rn(y2 - __bfloat162float(h23.x),
                                                   y3 - __bfloat162float(h23.y));
        h2[i] = make_uint2(bf2_bits(h01), bf2_bits(h23));
        l2[i] = make_uint2(bf2_bits(l01), bf2_bits(l23));
    }
}

// ================= bf16-split GEMM core: 128x256 CTA, 64x64 warp, KC=64 ======
// stage layout (96 KB): Ah[128x128B]@0  Al@16K  Bh[256x128B]@32K  Bl@64K
#define KC 64
#define ROWB 128
#define STAGE_B 98304
#define GEMM_SMEM (2 * STAGE_B)   // 192 KB, 2 stages

// EPI: 0 = split-store bf16 hi/lo, 1 = gelu + split-store, 2 = residual fp32
// Bh_/Bl_ pre-offset to this CTA's weight-row block; Nc = logical output width;
// c0 = output column base.
template <int EPI>
__device__ __forceinline__ void gemm_body(
    int Nc, int K, int m0, int c0,
    const bf16* __restrict__ Ah_, const bf16* __restrict__ Al_,
    const bf16* __restrict__ Bh_, const bf16* __restrict__ Bl_,
    const float* __restrict__ RES, float* __restrict__ Cf,
    bf16* __restrict__ Ch, bf16* __restrict__ Cl) {
    extern __shared__ char smem[];
    const uint32_t su = smem_to_u32(smem);

    const int t = threadIdx.x;
    const int lane = t & 31;
    const int wid = t >> 5;
    const int wm = wid & 1;
    const int wn = wid >> 1;

    // A staging: 128 rows x (hi|lo): thread t -> row t&127, part t>>7; 8 CP16
    const int arow = t & 127;
    const int apart = t >> 7;
    const bf16* Asrc = (apart ? Al_ : Ah_) + (size_t)(m0 + arow) * K;
    const uint32_t asw = ((uint32_t)(arow & 7)) << 4;
    const uint32_t adst = (uint32_t)apart * 16384u + (uint32_t)arow * ROWB;

    // B staging: 256 rows, each thread does hi+lo of its row; 16 CP16
    const bf16* Bhs = Bh_ + (size_t)t * K;
    const bf16* Bls = Bl_ + (size_t)t * K;
    const uint32_t bsw = ((uint32_t)(t & 7)) << 4;
    const uint32_t bdst = 32768u + (uint32_t)t * ROWB;

    auto CP_chunk = [&](int s, int k0) {
        const uint32_t st = su + (uint32_t)s * STAGE_B;
        #pragma unroll
        for (int c = 0; c < 8; c++) {
            CP16(st + adst + (((uint32_t)(c * 16)) ^ asw), Asrc + k0 + c * 8);
        }
        #pragma unroll
        for (int c = 0; c < 8; c++) {
            CP16(st + bdst + (((uint32_t)(c * 16)) ^ bsw), Bhs + k0 + c * 8);
            CP16(st + bdst + 32768u + (((uint32_t)(c * 16)) ^ bsw),
                 Bls + k0 + c * 8);
        }
    };

    float acc[4][8][4];
    #pragma unroll
    for (int mt = 0; mt < 4; mt++)
        #pragma unroll
        for (int nt = 0; nt < 8; nt++)
            #pragma unroll
            for (int j = 0; j < 4; j++) acc[mt][nt][j] = 0.f;

    const int nch = K / KC;
    CP_chunk(0, 0);
    CPCOMMIT();

    const int lrow16 = lane & 15;
    const int cg = (lane >> 4) & 1;

    for (int i = 0; i < nch; i++) {
        CPWAIT(0);
        __syncthreads();
        if (i + 1 < nch) {
            CP_chunk((i + 1) & 1, (i + 1) * KC);
            CPCOMMIT();
        }

        const uint32_t st = su + (uint32_t)(i & 1) * STAGE_B;

        #pragma unroll
        for (int ks = 0; ks < 4; ks++) {
            const uint32_t cbh = (uint32_t)(ks * 32 + cg * 16);
            uint32_t Ahf[4][4], Alf[4][4];
            #pragma unroll
            for (int mt = 0; mt < 4; mt++) {
                const int row = wm * 64 + mt * 16 + lrow16;
                const uint32_t swz = (uint32_t)(row & 7) << 4;
                const uint32_t base = st + (uint32_t)row * ROWB;
                ldsm_x4(base + (cbh ^ swz), Ahf[mt]);
                ldsm_x4(base + 16384u + (cbh ^ swz), Alf[mt]);
            }
            #pragma unroll
            for (int q = 0; q < 4; q++) {
                const int row = wn * 64 + q * 16 + lrow16;
                const uint32_t swz = (uint32_t)(row & 7) << 4;
                const uint32_t base = st + 32768u + (uint32_t)row * ROWB;
                uint32_t rh[4], rl[4];
                ldsm_x4(base + (cbh ^ swz), rh);
                ldsm_x4(base + 32768u + (cbh ^ swz), rl);
                uint32_t bh0[2] = {rh[0], rh[2]};
                uint32_t bh1[2] = {rh[1], rh[3]};
                uint32_t bl0[2] = {rl[0], rl[2]};
                uint32_t bl1[2] = {rl[1], rl[3]};
                #pragma unroll
                for (int mt = 0; mt < 4; mt++) {
                    mma_bf16(acc[mt][2 * q + 0], Ahf[mt], bh0);
                    mma_bf16(acc[mt][2 * q + 0], Ahf[mt], bl0);
                    mma_bf16(acc[mt][2 * q + 0], Alf[mt], bh0);
                    mma_bf16(acc[mt][2 * q + 1], Ahf[mt], bh1);
                    mma_bf16(acc[mt][2 * q + 1], Ahf[mt], bl1);
                    mma_bf16(acc[mt][2 * q + 1], Alf[mt], bh1);
                }
            }
        }
    }

    // ---- epilogue ----
    const int er0 = m0 + wm * 64 + (lane >> 2);
    const int ec0 = c0 + wn * 64 + (lane & 3) * 2;
    #pragma unroll
    for (int mt = 0; mt < 4; mt++) {
        #pragma unroll
        for (int g = 0; g < 2; g++) {
            const int row = er0 + mt * 16 + g * 8;
            #pragma unroll
            for (int nt = 0; nt < 8; nt++) {
                const int col = ec0 + nt * 8;
                float v0 = acc[mt][nt][g * 2 + 0];
                float v1 = acc[mt][nt][g * 2 + 1];
                size_t roff = (size_t)row * Nc + col;
                if (EPI == 2) {
                    float2 r = *reinterpret_cast<const float2*>(RES + roff);
                    *reinterpret_cast<float2*>(Cf + roff) =
                        make_float2(v0 + r.x, v1 + r.y);
                } else {
                    if (EPI == 1) {
                        v0 = 0.5f * v0 * (1.0f + erff(v0 * 0.70710678118654752f));
                        v1 = 0.5f * v1 * (1.0f + erff(v1 * 0.70710678118654752f));
                    }
                    __nv_bfloat162 hh = __floats2bfloat162_rn(v0, v1);
                    __nv_bfloat162 ll = __floats2bfloat162_rn(
                        v0 - __bfloat162float(hh.x), v1 - __bfloat162float(hh.y));
                    *reinterpret_cast<uint32_t*>(Ch + roff) = bf2_bits(hh);
                    *reinterpret_cast<uint32_t*>(Cl + roff) = bf2_bits(ll);
                }
            }
        }
    }
}

template <int EPI>
__global__ void __launch_bounds__(256, 1)
mma_gemm(int N, int K,
         const bf16* __restrict__ Ah_, const bf16* __restrict__ Al_,
         const bf16* __restrict__ Bh_, const bf16* __restrict__ Bl_,
         const float* __restrict__ RES, float* __restrict__ Cf,
         bf16* __restrict__ Ch, bf16* __restrict__ Cl) {
    const int n0 = blockIdx.x * 256;
    gemm_body<EPI>(N, K, blockIdx.y * 128, n0,
                   Ah_, Al_, Bh_ + (size_t)n0 * K, Bl_ + (size_t)n0 * K,
                   RES, Cf, Ch, Cl);
}

// Fused QKV: grid.x covers 3*D_MODEL columns; CTA selects its weight/output.
__global__ void __launch_bounds__(256, 1)
qkv_gemm(const bf16* __restrict__ hh, const bf16* __restrict__ hl,
         const bf16* __restrict__ wqh, const bf16* __restrict__ wql,
         const bf16* __restrict__ wkh, const bf16* __restrict__ wkl,
         const bf16* __restrict__ wvh, const bf16* __restrict__ wvl,
         bf16* __restrict__ qh, bf16* __restrict__ ql,
         bf16* __restrict__ kh, bf16* __restrict__ kl,
         bf16* __restrict__ vh, bf16* __restrict__ vl) {
    const int n0g = blockIdx.x * 256;
    const int sel = n0g >> 11;          // 0=q, 1=k, 2=v
    const int n0 = n0g & 2047;
    const bf16 *Bh, *Bl;
    bf16 *Ch, *Cl;
    if (sel == 0)      { Bh = wqh; Bl = wql; Ch = qh; Cl = ql; }
    else if (sel == 1) { Bh = wkh; Bl = wkl; Ch = kh; Cl = kl; }
    else               { Bh = wvh; Bl = wvl; Ch = vh; Cl = vl; }
    gemm_body<0>(D_MODEL, D_MODEL, blockIdx.y * 128, n0,
                 hh, hl, Bh + (size_t)n0 * D_MODEL, Bl + (size_t)n0 * D_MODEL,
                 nullptr, nullptr, Ch, Cl);
}

// ================= tensor-core flash attention (bf16 split inputs) ===========
#define ATT_BUF0 65536
#define ATT_MASK 131072
#define ATT_SMEM_BYTES (131072 + 512)

__device__ __forceinline__ void att_stage_chunk(
    char* smem, uint32_t sb, uint32_t bufoff,
    const bf16* __restrict__ Kh, const bf16* __restrict__ Kl,
    const bf16* __restrict__ Vh, const bf16* __restrict__ Vl,
    const int* __restrict__ bm, int kv0, int slot, int t) {
    {
        const int row = t >> 2;
        const int dq = (t & 3) * 32;
        const size_t goff = (size_t)(kv0 + row) * D_MODEL + dq;
        const uint32_t rbase = sb + bufoff + (uint32_t)row * 256;
        const uint32_t swr = (uint32_t)(row & 7) << 4;
        #pragma unroll
        for (int i = 0; i < 4; i++) {
            const uint32_t off = ((uint32_t)(dq * 2 + i * 16)) ^ swr;
            CP16(rbase + off, Kh + goff + i * 8);
            CP16(rbase + 16384 + off, Kl + goff + i * 8);
        }
    }
    {
        const int kvp = t & 31;
        const int dblk = t >> 5;
        const size_t r0 = (size_t)(kv0 + 2 * kvp) * D_MODEL + dblk * 16;
        const size_t r1 = r0 + D_MODEL;
        uint4 h0a = *reinterpret_cast<const uint4*>(Vh + r0);
        uint4 h0b = *reinterpret_cast<const uint4*>(Vh + r0 + 8);
        uint4 h1a = *reinterpret_cast<const uint4*>(Vh + r1);
        uint4 h1b = *reinterpret_cast<const uint4*>(Vh + r1 + 8);
        uint4 l0a = *reinterpret_cast<const uint4*>(Vl + r0);
        uint4 l0b = *reinterpret_cast<const uint4*>(Vl + r0 + 8);
        uint4 l1a = *reinterpret_cast<const uint4*>(Vl + r1);
        uint4 l1b = *reinterpret_cast<const uint4*>(Vl + r1 + 8);
        uint32_t h0[8] = {h0a.x, h0a.y, h0a.z, h0a.w, h0b.x, h0b.y, h0b.z, h0b.w};
        uint32_t h1[8] = {h1a.x, h1a.y, h1a.z, h1a.w, h1b.x, h1b.y, h1b.z, h1b.w};
        uint32_t l0[8] = {l0a.x, l0a.y, l0a.z, l0a.w, l0b.x, l0b.y, l0b.z, l0b.w};
        uint32_t l1[8] = {l1a.x, l1a.y, l1a.z, l1a.w, l1b.x, l1b.y, l1b.z, l1b.w};
        const uint32_t koff = (uint32_t)(kvp * 4);
        #pragma unroll
        for (int dd = 0; dd < 8; dd++) {
            const int d0 = dblk * 16 + dd * 2;
            const uint32_t vb0 = sb + bufoff + 32768 + (uint32_t)d0 * 128 +
                                 (koff ^ ((uint32_t)(d0 & 7) << 4));
            const uint32_t vb1 = sb + bufoff + 32768 + (uint32_t)(d0 + 1) * 128 +
                                 (koff ^ ((uint32_t)((d0 + 1) & 7) << 4));
            asm volatile("st.shared.b32 [%0], %1;" :: "r"(vb0),
                         "r"(__byte_perm(h0[dd], h1[dd], 0x5410)) : "memory");
            asm volatile("st.shared.b32 [%0], %1;" :: "r"(vb1),
                         "r"(__byte_perm(h0[dd], h1[dd], 0x7632)) : "memory");
            asm volatile("st.shared.b32 [%0], %1;" :: "r"(vb0 + 16384),
                         "r"(__byte_perm(l0[dd], l1[dd], 0x5410)) : "memory");
            asm volatile("st.shared.b32 [%0], %1;" :: "r"(vb1 + 16384),
                         "r"(__byte_perm(l0[dd], l1[dd], 0x7632)) : "memory");
        }
    }
    if (t < 64)
        reinterpret_cast<int*>(smem + ATT_MASK + slot * 256)[t] = bm[kv0 + t];
}

__global__ void __launch_bounds__(256, 1)
flash_attn_tc(const bf16* __restrict__ Qh, const bf16* __restrict__ Ql,
              const bf16* __restrict__ Kh, const bf16* __restrict__ Kl,
              const bf16* __restrict__ Vh, const bf16* __restrict__ Vl,
              const int* __restrict__ mask,
              bf16* __restrict__ Oh, bf16* __restrict__ Ol) {
    extern __shared__ char smem[];
    const uint32_t sb = smem_to_u32(smem);
    const int t = threadIdx.x, lane = t & 31, w = t >> 5;
    const int qi = gridDim.x - 1 - blockIdx.x;
    const int h = blockIdx.y, b = blockIdx.z;
    const int q0 = qi * 128;
    const size_t base = (size_t)b * SEQ * D_MODEL + (size_t)h * HEAD_DIM;
    const int* bm = mask + b * SEQ;
    const float scale = 0.08838834764831845f;

    {
        const int row = t >> 1, half = t & 1;
        const size_t goff = base + (size_t)(q0 + row) * D_MODEL + half * 64;
        const uint4* ghv = reinterpret_cast<const uint4*>(Qh + goff);
        const uint4* glv = reinterpret_cast<const uint4*>(Ql + goff);
        char* qr = smem + (uint32_t)row * 256;
        const uint32_t swr = (uint32_t)(row & 7) << 4;
        #pragma unroll
        for (int i = 0; i < 8; i++) {
            const uint32_t off = ((uint32_t)(half * 128 + i * 16)) ^ swr;
            *reinterpret_cast<uint4*>(qr + off) = ghv[i];
            *reinterpret_cast<uint4*>(qr + 32768 + off) = glv[i];
        }
    }
    att_stage_chunk(smem, sb, ATT_BUF0, Kh + base, Kl + base,
                    Vh + base, Vl + base, bm, 0, 0, t);
    CPCOMMIT();
    CPWAIT(0);
    __syncthreads();

    uint32_t Aqh[8][4], Aql[8][4];
    {
        const int r = w * 16 + (lane & 15);
        const uint32_t swz = (uint32_t)(r & 7) << 4;
        const uint32_t cgo = ((uint32_t)(lane >> 4)) << 4;
        const uint32_t qb = sb + (uint32_t)r * 256;
        #pragma unroll
        for (int ds = 0; ds < 8; ds++) {
            const uint32_t off = (((uint32_t)(ds * 32)) + cgo) ^ swz;
            ldsm_x4(qb + off, Aqh[ds]);
            ldsm_x4(qb + 32768 + off, Aql[ds]);
        }
    }
    __syncthreads();

    float m1 = -1e30f, l1 = 0.f, m2 = -1e30f, l2 = 0.f;
    float acc[16][4];
    #pragma unroll
    for (int nt = 0; nt < 16; nt++)
        #pragma unroll
        for (int c = 0; c < 4; c++) acc[nt][c] = 0.f;

    const int r1g = q0 + w * 16 + (lane >> 2);
    const int r2g = r1g + 8;
    const int nch = 2 * qi + 2;
    const uint32_t cgo = ((uint32_t)(lane >> 4)) << 4;

    for (int j = 0; j < nch; j++) {
        const int s = j & 1;
        const uint32_t bufo = s ? 0u : (uint32_t)ATT_BUF0;
        const int kv0 = j * 64;

        if (j + 1 < nch) {
            att_stage_chunk(smem, sb, s ? (uint32_t)ATT_BUF0 : 0u,
                            Kh + base, Kl + base, Vh + base, Vl + base,
                            bm, kv0 + 64, (j + 1) & 1, t);
            CPCOMMIT();
        }

        float sacc[8][4];
        #pragma unroll
        for (int nt = 0; nt < 8; nt++)
            #pragma unroll
            for (int c = 0; c < 4; c++) sacc[nt][c] = 0.f;

        #pragma unroll
        for (int g4 = 0; g4 < 4; g4++) {
            const int kr = g4 * 16 + (lane & 15);
            const uint32_t swz = (uint32_t)(kr & 7) << 4;
            const uint32_t kb = sb + bufo + (uint32_t)kr * 256;
            #pragma unroll
            for (int ds = 0; ds < 8; ds++) {
                const uint32_t off = (((uint32_t)(ds * 32)) + cgo) ^ swz;
                uint32_t rh[4], rl[4];
                ldsm_x4(kb + off, rh);
                ldsm_x4(kb + 16384 + off, rl);
                uint32_t bh0[2] = {rh[0], rh[2]}, bh1[2] = {rh[1], rh[3]};
                uint32_t bl0[2] = {rl[0], rl[2]}, bl1[2] = {rl[1], rl[3]};
                mma_bf16(sacc[2 * g4 + 0], Aqh[ds], bh0);
                mma_bf16(sacc[2 * g4 + 0], Aqh[ds], bl0);
                mma_bf16(sacc[2 * g4 + 0], Aql[ds], bh0);
                mma_bf16(sacc[2 * g4 + 1], Aqh[ds], bh1);
                mma_bf16(sacc[2 * g4 + 1], Aqh[ds], bl1);
                mma_bf16(sacc[2 * g4 + 1], Aql[ds], bh1);
            }
        }

        const int* mrow = reinterpret_cast<const int*>(smem + ATT_MASK + s * 256);
        #pragma unroll
        for (int nt = 0; nt < 8; nt++) {
            const int c0 = nt * 8 + (lane & 3) * 2;
            const int k0g = kv0 + c0, k1g = k0g + 1;
            const bool mv0 = mrow[c0] != 0, mv1 = mrow[c0 + 1] != 0;
            float v0 = sacc[nt][0] * scale, v1 = sacc[nt][1] * scale;
            float v2 = sacc[nt][2] * scale, v3 = sacc[nt][3] * scale;
            sacc[nt][0] = (k0g > r1g || !mv0) ? -1e9f : v0;
            sacc[nt][1] = (k1g > r1g || !mv1) ? -1e9f : v1;
            sacc[nt][2] = (k0g > r2g || !mv0) ? -1e9f : v2;
            sacc[nt][3] = (k1g > r2g || !mv1) ? -1e9f : v3;
        }

        float mx1 = -1e30f, mx2 = -1e30f;
        #pragma unroll
        for (int nt = 0; nt < 8; nt++) {
            mx1 = fmaxf(mx1, fmaxf(sacc[nt][0], sacc[nt][1]));
            mx2 = fmaxf(mx2, fmaxf(sacc[nt][2], sacc[nt][3]));
        }
        mx1 = fmaxf(mx1, __shfl_xor_sync(0xFFFFFFFFu, mx1, 1));
        mx1 = fmaxf(mx1, __shfl_xor_sync(0xFFFFFFFFu, mx1, 2));
        mx2 = fmaxf(mx2, __shfl_xor_sync(0xFFFFFFFFu, mx2, 1));
        mx2 = fmaxf(mx2, __shfl_xor_sync(0xFFFFFFFFu, mx2, 2));
        const float m1n = fmaxf(m1, mx1), m2n = fmaxf(m2, mx2);
        const float a1 = __expf(m1 - m1n), a2 = __expf(m2 - m2n);
        float s1 = 0.f, s2 = 0.f;
        #pragma unroll
        for (int nt = 0; nt < 8; nt++) {
            sacc[nt][0] = __expf(sacc[nt][0] - m1n);
            sacc[nt][1] = __expf(sacc[nt][1] - m1n);
            sacc[nt][2] = __expf(sacc[nt][2] - m2n);
            sacc[nt][3] = __expf(sacc[nt][3] - m2n);
            s1 += sacc[nt][0] + sacc[nt][1];
            s2 += sacc[nt][2] + sacc[nt][3];
        }
        s1 += __shfl_xor_sync(0xFFFFFFFFu, s1, 1);
        s1 += __shfl_xor_sync(0xFFFFFFFFu, s1, 2);
        s2 += __shfl_xor_sync(0xFFFFFFFFu, s2, 1);
        s2 += __shfl_xor_sync(0xFFFFFFFFu, s2, 2);
        l1 = l1 * a1 + s1; m1 = m1n;
        l2 = l2 * a2 + s2; m2 = m2n;
        #pragma unroll
        for (int nt = 0; nt < 16; nt++) {
            acc[nt][0] *= a1; acc[nt][1] *= a1;
            acc[nt][2] *= a2; acc[nt][3] *= a2;
        }

        #pragma unroll
        for (int ks = 0; ks < 4; ks++) {
            const float* p0 = sacc[2 * ks];
            const float* p1 = sacc[2 * ks + 1];
            __nv_bfloat162 h0 = __floats2bfloat162_rn(p0[0], p0[1]);
            __nv_bfloat162 h1 = __floats2bfloat162_rn(p0[2], p0[3]);
            __nv_bfloat162 h2 = __floats2bfloat162_rn(p1[0], p1[1]);
            __nv_bfloat162 h3 = __floats2bfloat162_rn(p1[2], p1[3]);
            uint32_t pa_h[4] = {bf2_bits(h0), bf2_bits(h1), bf2_bits(h2), bf2_bits(h3)};
            __nv_bfloat162 e0 = __floats2bfloat162_rn(
                p0[0] - __bfloat162float(h0.x), p0[1] - __bfloat162float(h0.y));
            __nv_bfloat162 e1 = __floats2bfloat162_rn(
                p0[2] - __bfloat162float(h1.x), p0[3] - __bfloat162float(h1.y));
            __nv_bfloat162 e2 = __floats2bfloat162_rn(
                p1[0] - __bfloat162float(h2.x), p1[1] - __bfloat162float(h2.y));
            __nv_bfloat162 e3 = __floats2bfloat162_rn(
                p1[2] - __bfloat162float(h3.x), p1[3] - __bfloat162float(h3.y));
            uint32_t pa_l[4] = {bf2_bits(e0), bf2_bits(e1), bf2_bits(e2), bf2_bits(e3)};

            #pragma unroll
            for (int gd = 0; gd < 8; gd++) {
                const int dr = gd * 16 + (lane & 15);
                const uint32_t swz = (uint32_t)(dr & 7) << 4;
                const uint32_t off = (((uint32_t)(ks * 32)) + cgo) ^ swz;
                const uint32_t vb = sb + bufo + 32768 + (uint32_t)dr * 128;
                uint32_t rh[4], rl[4];
                ldsm_x4(vb + off, rh);
                ldsm_x4(vb + 16384 + off, rl);
                uint32_t bh0[2] = {rh[0], rh[2]}, bh1[2] = {rh[1], rh[3]};
                uint32_t bl0[2] = {rl[0], rl[2]}, bl1[2] = {rl[1], rl[3]};
                mma_bf16(acc[2 * gd + 0], pa_h, bh0);
                mma_bf16(acc[2 * gd + 0], pa_h, bl0);
                mma_bf16(acc[2 * gd + 0], pa_l, bh0);
                mma_bf16(acc[2 * gd + 1], pa_h, bh1);
                mma_bf16(acc[2 * gd + 1], pa_h, bl1);
                mma_bf16(acc[2 * gd + 1], pa_l, bh1);
            }
        }

        CPWAIT(0);
        __syncthreads();
    }

    const float i1 = (l1 > 0.f) ? 1.f / l1 : 0.f;
    const float i2 = (l2 > 0.f) ? 1.f / l2 : 0.f;
    #pragma unroll
    for (int nt = 0; nt < 16; nt++) {
        const int col = nt * 8 + (lane & 3) * 2;
        {
            float o0 = acc[nt][0] * i1, o1 = acc[nt][1] * i1;
            __nv_bfloat162 hh = __floats2bfloat162_rn(o0, o1);
            __nv_bfloat162 ll = __floats2bfloat162_rn(
                o0 - __bfloat162float(hh.x), o1 - __bfloat162float(hh.y));
            size_t off = base + (size_t)r1g * D_MODEL + col;
            *reinterpret_cast<uint32_t*>(Oh + off) = bf2_bits(hh);
            *reinterpret_cast<uint32_t*>(Ol + off) = bf2_bits(ll);
        }
        {
            float o0 = acc[nt][2] * i2, o1 = acc[nt][3] * i2;
            __nv_bfloat162 hh = __floats2bfloat162_rn(o0, o1);
            __nv_bfloat162 ll = __floats2bfloat162_rn(
                o0 - __bfloat162float(hh.x), o1 - __bfloat162float(hh.y));
            size_t off = base + (size_t)r2g * D_MODEL + col;
            *reinterpret_cast<uint32_t*>(Oh + off) = bf2_bits(hh);
            *reinterpret_cast<uint32_t*>(Ol + off) = bf2_bits(ll);
        }
    }
}

// ---------------- launch -----------------------------------------------------
extern "C" void kernel_launch(void* const* d_in, const int* in_sizes, int n_in,
                              void* d_out, int out_size) {
    const float* x           = (const float*)d_in[0];
    const int*   attn_mask   = (const int*)  d_in[1];
    const float* w_norm_attn = (const float*)d_in[2];
    const float* wq          = (const float*)d_in[3];
    const float* wk          = (const float*)d_in[4];
    const float* wv          = (const float*)d_in[5];
    const float* wo          = (const float*)d_in[6];
    const float* w_norm_mlp  = (const float*)d_in[7];
    const float* w_up        = (const float*)d_in[8];
    const float* w_down      = (const float*)d_in[9];
    float* out = (float*)d_out;

    bf16 *h_hi, *h_lo, *q_hi, *q_lo, *k_hi, *k_lo, *v_hi, *v_lo;
    bf16 *att_hi, *att_lo, *up_hi, *up_lo;
    bf16 *wq_hi, *wq_lo, *wk_hi, *wk_lo, *wv_hi, *wv_lo, *wo_hi, *wo_lo;
    bf16 *wu_hi, *wu_lo, *wd_hi, *wd_lo;
    float* x1;
    cudaGetSymbolAddress((void**)&h_hi, g_h_hi);   cudaGetSymbolAddress((void**)&h_lo, g_h_lo);
    cudaGetSymbolAddress((void**)&q_hi, g_q_hi);   cudaGetSymbolAddress((void**)&q_lo, g_q_lo);
    cudaGetSymbolAddress((void**)&k_hi, g_k_hi);   cudaGetSymbolAddress((void**)&k_lo, g_k_lo);
    cudaGetSymbolAddress((void**)&v_hi, g_v_hi);   cudaGetSymbolAddress((void**)&v_lo, g_v_lo);
    cudaGetSymbolAddress((void**)&att_hi, g_att_hi); cudaGetSymbolAddress((void**)&att_lo, g_att_lo);
    cudaGetSymbolAddress((void**)&up_hi, g_up_hi); cudaGetSymbolAddress((void**)&up_lo, g_up_lo);
    cudaGetSymbolAddress((void**)&wq_hi, g_wq_hi); cudaGetSymbolAddress((void**)&wq_lo, g_wq_lo);
    cudaGetSymbolAddress((void**)&wk_hi, g_wk_hi); cudaGetSymbolAddress((void**)&wk_lo, g_wk_lo);
    cudaGetSymbolAddress((void**)&wv_hi, g_wv_hi); cudaGetSymbolAddress((void**)&wv_lo, g_wv_lo);
    cudaGetSymbolAddress((void**)&wo_hi, g_wo_hi); cudaGetSymbolAddress((void**)&wo_lo, g_wo_lo);
    cudaGetSymbolAddress((void**)&wu_hi, g_wu_hi); cudaGetSymbolAddress((void**)&wu_lo, g_wu_lo);
    cudaGetSymbolAddress((void**)&wd_hi, g_wd_hi); cudaGetSymbolAddress((void**)&wd_lo, g_wd_lo);
    cudaGetSymbolAddress((void**)&x1, g_x1);

    cudaFuncSetAttribute(flash_attn_tc,
                         cudaFuncAttributeMaxDynamicSharedMemorySize, ATT_SMEM_BYTES);
    cudaFuncSetAttribute(qkv_gemm,
                         cudaFuncAttributeMaxDynamicSharedMemorySize, GEMM_SMEM);
    cudaFuncSetAttribute(mma_gemm<1>,
                         cudaFuncAttributeMaxDynamicSharedMemorySize, GEMM_SMEM);
    cudaFuncSetAttribute(mma_gemm<2>,
                         cudaFuncAttributeMaxDynamicSharedMemorySize, GEMM_SMEM);

    // 0) split weights to bf16 hi/lo
    const int DD4 = D_MODEL * D_MODEL / 4;
    const int UD4 = MLP_DIM * D_MODEL / 4;
    split_dd<<<dim3((DD4 + 255) / 256, 4), 256>>>(wq, wk, wv, wo,
        wq_hi, wq_lo, wk_hi, wk_lo, wv_hi, wv_lo, wo_hi, wo_lo);
    split_ud<<<dim3((UD4 + 255) / 256, 2), 256>>>(w_up, w_down,
        wu_hi, wu_lo, wd_hi, wd_lo);

    // 1) rmsnorm(x) -> h (bf16 hi/lo)
    rmsnorm_split<<<TOK, 256>>>(x, w_norm_attn, h_hi, h_lo);

    // 2) fused q,k,v projection
    dim3 gQKV(3 * D_MODEL / 256, TOK / 128);
    qkv_gemm<<<gQKV, 256, GEMM_SMEM>>>(h_hi, h_lo,
        wq_hi, wq_lo, wk_hi, wk_lo, wv_hi, wv_lo,
        q_hi, q_lo, k_hi, k_lo, v_hi, v_lo);

    // 3) attention (bf16 split in/out)
    dim3 gA(SEQ / 128, N_HEADS, BATCH);
    flash_attn_tc<<<gA, 256, ATT_SMEM_BYTES>>>(q_hi, q_lo, k_hi, k_lo,
                                               v_hi, v_lo, attn_mask,
                                               att_hi, att_lo);

    // 4) output projection + residual -> x1 (fp32)   [launch #6: profiled]
    dim3 gD(D_MODEL / 256, TOK / 128);
    mma_gemm<2><<<gD, 256, GEMM_SMEM>>>(D_MODEL, D_MODEL,
        att_hi, att_lo, wo_hi, wo_lo, x, x1, nullptr, nullptr);

    // 5) rmsnorm(x1) -> h (bf16 hi/lo)
    rmsnorm_split<<<TOK, 256>>>(x1, w_norm_mlp, h_hi, h_lo);

    // 6) up projection + gelu (split-store)
    dim3 gU(MLP_DIM / 256, TOK / 128);
    mma_gemm<1><<<gU, 256, GEMM_SMEM>>>(MLP_DIM, D_MODEL,
        h_hi, h_lo, wu_hi, wu_lo, nullptr, nullptr, up_hi, up_lo);

    // 7) down projection + residual -> out (fp32)
    mma_gemm<2><<<gD, 256, GEMM_SMEM>>>(D_MODEL, MLP_DIM,
        up_hi, up_lo, wd_hi, wd_lo, x1, out, nullptr, nullptr);
}

// round 9
// speedup vs baseline: 1.2760x; 1.2760x over previous
#include <cuda_runtime.h>
#include <cuda_bf16.h>
#include <math.h>
#include <stdint.h>

#define D_MODEL 2048
#define N_HEADS 16
#define HEAD_DIM 128
#define MLP_DIM 8192
#define BATCH 2
#define SEQ 2048
#define TOK (BATCH * SEQ)

// ---------------- scratch (static device globals; fp32, tf32-rounded) -------
__device__ float g_h[(size_t)TOK * D_MODEL];
__device__ float g_q[(size_t)TOK * D_MODEL];
__device__ float g_k[(size_t)TOK * D_MODEL];
__device__ float g_v[(size_t)TOK * D_MODEL];
__device__ float g_att[(size_t)TOK * D_MODEL];
__device__ float g_up[(size_t)TOK * MLP_DIM];
__device__ float g_x1[(size_t)TOK * D_MODEL];
__device__ float g_wq[(size_t)D_MODEL * D_MODEL];
__device__ float g_wk[(size_t)D_MODEL * D_MODEL];
__device__ float g_wv[(size_t)D_MODEL * D_MODEL];
__device__ float g_wo[(size_t)D_MODEL * D_MODEL];
__device__ float g_wu[(size_t)MLP_DIM * D_MODEL];
__device__ float g_wd[(size_t)D_MODEL * MLP_DIM];

// ================= PTX helpers (baseline PTX, sm_80+) =======================
__device__ __forceinline__ uint32_t smem_to_u32(const void* p) {
    uint32_t a;
    asm("{ .reg .u64 t; cvta.to.shared.u64 t, %1; cvt.u32.u64 %0, t; }"
        : "=r"(a) : "l"(p));
    return a;
}
__device__ __forceinline__ void ldsm_x4(uint32_t addr, uint32_t* r) {
    asm volatile("ldmatrix.sync.aligned.m8n8.x4.shared.b16 {%0,%1,%2,%3}, [%4];"
                 : "=r"(r[0]), "=r"(r[1]), "=r"(r[2]), "=r"(r[3]) : "r"(addr));
}
// tf32 mma: D(16x8) += A(16x8) * B(8x8), A row-major, B col-major (NT)
__device__ __forceinline__ void mma_tf32(float* d, const uint32_t* a,
                                         const uint32_t* b) {
    asm volatile(
        "mma.sync.aligned.m16n8k8.row.col.f32.tf32.tf32.f32 "
        "{%0,%1,%2,%3}, {%4,%5,%6,%7}, {%8,%9}, {%0,%1,%2,%3};"
        : "+f"(d[0]), "+f"(d[1]), "+f"(d[2]), "+f"(d[3])
        : "r"(a[0]), "r"(a[1]), "r"(a[2]), "r"(a[3]), "r"(b[0]), "r"(b[1]));
}
__device__ __forceinline__ uint32_t tf32_bits(float x) {
    uint32_t u;
    asm("cvt.rna.tf32.f32 %0, %1;" : "=r"(u) : "f"(x));
    return u;
}
__device__ __forceinline__ float tf32f(float x) {
    return __uint_as_float(tf32_bits(x));
}
#define CP16(dst, src) \
    asm volatile("cp.async.cg.shared.global [%0], [%1], 16;" \
                 :: "r"(dst), "l"(src) : "memory")
#define CPCOMMIT() asm volatile("cp.async.commit_group;" ::: "memory")
#define CPWAIT(n)  asm volatile("cp.async.wait_group %0;" :: "n"(n) : "memory")
#define STS64F(addr, x, y) \
    asm volatile("st.shared.v2.f32 [%0], {%1, %2};" \
                 :: "r"(addr), "f"(x), "f"(y) : "memory")
#define STS64U(addr, x, y) \
    asm volatile("st.shared.v2.b32 [%0], {%1, %2};" \
                 :: "r"(addr), "r"(x), "r"(y) : "memory")

// ================= weight rounding to tf32 (once) ============================
__device__ __forceinline__ void round_store(const float* src, float* dst, int i) {
    float4 v = reinterpret_cast<const float4*>(src)[i];
    reinterpret_cast<float4*>(dst)[i] =
        make_float4(tf32f(v.x), tf32f(v.y), tf32f(v.z), tf32f(v.w));
}
__global__ void round_dd(const float* __restrict__ wq, const float* __restrict__ wk,
                         const float* __restrict__ wv, const float* __restrict__ wo,
                         float* oq, float* ok, float* ov, float* oo) {
    int i = blockIdx.x * blockDim.x + threadIdx.x;
    if (i >= D_MODEL * D_MODEL / 4) return;
    switch (blockIdx.y) {
        case 0: round_store(wq, oq, i); break;
        case 1: round_store(wk, ok, i); break;
        case 2: round_store(wv, ov, i); break;
        default: round_store(wo, oo, i); break;
    }
}
__global__ void round_ud(const float* __restrict__ wu, const float* __restrict__ wd,
                         float* ou, float* od) {
    int i = blockIdx.x * blockDim.x + threadIdx.x;
    if (i >= MLP_DIM * D_MODEL / 4) return;
    if (blockIdx.y == 0) round_store(wu, ou, i);
    else                 round_store(wd, od, i);
}

// ================= RMSNorm -> tf32-rounded fp32 ==============================
__global__ void rmsnorm_tf32(const float* __restrict__ x,
                             const float* __restrict__ w,
                             float* __restrict__ out) {
    int row = blockIdx.x;
    const float4* xr = reinterpret_cast<const float4*>(x + (size_t)row * D_MODEL);
    const float4* w4 = reinterpret_cast<const float4*>(w);

    float ss = 0.f;
    for (int i = threadIdx.x; i < D_MODEL / 4; i += blockDim.x) {
        float4 v = xr[i];
        ss += v.x * v.x + v.y * v.y + v.z * v.z + v.w * v.w;
    }
    for (int off = 16; off > 0; off >>= 1)
        ss += __shfl_xor_sync(0xFFFFFFFFu, ss, off);
    __shared__ float red[8];
    __shared__ float s_rms;
    int lane = threadIdx.x & 31, wid = threadIdx.x >> 5;
    if (lane == 0) red[wid] = ss;
    __syncthreads();
    if (threadIdx.x == 0) {
        float tt = 0.f;
        #pragma unroll
        for (int i = 0; i < 8; i++) tt += red[i];
        s_rms = rsqrtf(tt / (float)D_MODEL + 1e-6f);
    }
    __syncthreads();
    float r = s_rms;
    float4* o4 = reinterpret_cast<float4*>(out + (size_t)row * D_MODEL);
    for (int i = threadIdx.x; i < D_MODEL / 4; i += blockDim.x) {
        float4 v = xr[i];
        float4 ww = w4[i];
        o4[i] = make_float4(tf32f(v.x * r * ww.x), tf32f(v.y * r * ww.y),
                            tf32f(v.z * r * ww.z), tf32f(v.w * r * ww.w));
    }
}

// ================= TF32 GEMM: 128x256 CTA, 64x64 warp, KC=32 =================
// C[M,Nc-slice] = A[M,K] @ B[N,K]^T  (single-pass tf32, fp32 accumulate)
// EPI: 0 = tf32-rounded store, 1 = gelu + tf32-rounded store, 2 = residual fp32
#define KC 32
#define ROWB 128
#define A_TILE 16384            // 128 rows x 128B
#define B_TILE 32768            // 256 rows x 128B
#define STAGE_B (A_TILE + B_TILE)
#define NSTAGE 4
#define GEMM_SMEM (NSTAGE * STAGE_B)   // 192 KB

template <int EPI>
__device__ __forceinline__ void gemm_body(
    int Nc, int K, int m0, int c0,
    const float* __restrict__ A, const float* __restrict__ B,  // B pre-offset
    const float* __restrict__ RES, float* __restrict__ Cf,
    float* __restrict__ Ct) {
    extern __shared__ char smem[];
    const uint32_t su = smem_to_u32(smem);

    const int t = threadIdx.x;
    const int lane = t & 31;
    const int wid = t >> 5;
    const int wm = wid & 1;
    const int wn = wid >> 1;

    // A staging: row = t>>1, half = t&1 covers 64B; 4 CP16
    const int arow = t >> 1;
    const int ahalf = t & 1;
    const float* Asrc = A + (size_t)(m0 + arow) * K + ahalf * 16;
    const uint32_t asw = ((uint32_t)(arow & 7)) << 4;
    const uint32_t adst = (uint32_t)arow * ROWB;

    // B staging: row = t covers full 128B row; 8 CP16
    const float* Bsrc = B + (size_t)t * K;
    const uint32_t bsw = ((uint32_t)(t & 7)) << 4;
    const uint32_t bdst = (uint32_t)A_TILE + (uint32_t)t * ROWB;

    auto CP_chunk = [&](int s, int k0) {
        const uint32_t st = su + (uint32_t)s * STAGE_B;
        #pragma unroll
        for (int c = 0; c < 4; c++)
            CP16(st + adst + (((uint32_t)(ahalf * 64 + c * 16)) ^ asw),
                 Asrc + k0 + c * 4);
        #pragma unroll
        for (int c = 0; c < 8; c++)
            CP16(st + bdst + (((uint32_t)(c * 16)) ^ bsw), Bsrc + k0 + c * 4);
    };

    float acc[4][8][4];
    #pragma unroll
    for (int mt = 0; mt < 4; mt++)
        #pragma unroll
        for (int nt = 0; nt < 8; nt++)
            #pragma unroll
            for (int j = 0; j < 4; j++) acc[mt][nt][j] = 0.f;

    const int nch = K / KC;
    #pragma unroll
    for (int s = 0; s < NSTAGE - 1; s++) {
        CP_chunk(s, s * KC);
        CPCOMMIT();
    }

    // ldmatrix lane mapping (M1): m0=lanes0-7 rows lo k0, m1=8-15 rows lo k+16B,
    // m2=16-23 rows hi k0, m3=24-31 rows hi k+16B
    const int subrow = (lane & 7) | (((lane >> 4) & 1) << 3);
    const uint32_t klane = (uint32_t)(((lane >> 3) & 1) << 4);

    for (int i = 0; i < nch; i++) {
        CPWAIT(NSTAGE - 2);
        __syncthreads();

        const uint32_t st = su + (uint32_t)(i % NSTAGE) * STAGE_B;

        #pragma unroll
        for (int ks = 0; ks < 4; ks++) {
            const uint32_t ko = (uint32_t)(ks * 32) + klane;
            uint32_t Af[4][4];
            #pragma unroll
            for (int mt = 0; mt < 4; mt++) {
                const int row = wm * 64 + mt * 16 + subrow;
                uint32_t r[4];
                ldsm_x4(st + (uint32_t)row * ROWB +
                        (ko ^ (((uint32_t)(row & 7)) << 4)), r);
                Af[mt][0] = r[0]; Af[mt][1] = r[2];  // a0,a1 = (lo,k0),(hi,k0)
                Af[mt][2] = r[1]; Af[mt][3] = r[3];  // a2,a3 = (lo,k4),(hi,k4)
            }
            #pragma unroll
            for (int q = 0; q < 4; q++) {
                const int row = wn * 64 + q * 16 + subrow;
                uint32_t r[4];
                ldsm_x4(st + A_TILE + (uint32_t)row * ROWB +
                        (ko ^ (((uint32_t)(row & 7)) << 4)), r);
                uint32_t b0[2] = {r[0], r[1]};  // n lo8: b0,b1
                uint32_t b1[2] = {r[2], r[3]};  // n hi8
                #pragma unroll
                for (int mt = 0; mt < 4; mt++) {
                    mma_tf32(acc[mt][2 * q + 0], Af[mt], b0);
                    mma_tf32(acc[mt][2 * q + 1], Af[mt], b1);
                }
            }
        }

        if (i + NSTAGE - 1 < nch)
            CP_chunk((i + NSTAGE - 1) % NSTAGE, (i + NSTAGE - 1) * KC);
        CPCOMMIT();
    }

    // ---- epilogue ----
    const int er0 = m0 + wm * 64 + (lane >> 2);
    const int ec0 = c0 + wn * 64 + (lane & 3) * 2;
    #pragma unroll
    for (int mt = 0; mt < 4; mt++) {
        #pragma unroll
        for (int g = 0; g < 2; g++) {
            const int row = er0 + mt * 16 + g * 8;
            #pragma unroll
            for (int nt = 0; nt < 8; nt++) {
                const int col = ec0 + nt * 8;
                float v0 = acc[mt][nt][g * 2 + 0];
                float v1 = acc[mt][nt][g * 2 + 1];
                size_t roff = (size_t)row * Nc + col;
                if (EPI == 2) {
                    float2 r = *reinterpret_cast<const float2*>(RES + roff);
                    *reinterpret_cast<float2*>(Cf + roff) =
                        make_float2(v0 + r.x, v1 + r.y);
                } else {
                    if (EPI == 1) {
                        v0 = 0.5f * v0 * (1.0f + erff(v0 * 0.70710678118654752f));
                        v1 = 0.5f * v1 * (1.0f + erff(v1 * 0.70710678118654752f));
                    }
                    *reinterpret_cast<float2*>(Ct + roff) =
                        make_float2(tf32f(v0), tf32f(v1));
                }
            }
        }
    }
}

template <int EPI>
__global__ void __launch_bounds__(256, 1)
mma_gemm(int N, int K,
         const float* __restrict__ A, const float* __restrict__ B,
         const float* __restrict__ RES, float* __restrict__ Cf,
         float* __restrict__ Ct) {
    const int n0 = blockIdx.x * 256;
    gemm_body<EPI>(N, K, blockIdx.y * 128, n0, A, B + (size_t)n0 * K,
                   RES, Cf, Ct);
}

// Fused QKV
__global__ void __launch_bounds__(256, 1)
qkv_gemm(const float* __restrict__ h,
         const float* __restrict__ wq, const float* __restrict__ wk,
         const float* __restrict__ wv,
         float* __restrict__ q, float* __restrict__ k, float* __restrict__ v) {
    const int n0g = blockIdx.x * 256;
    const int sel = n0g >> 11;
    const int n0 = n0g & 2047;
    const float* B;
    float* C;
    if (sel == 0)      { B = wq; C = q; }
    else if (sel == 1) { B = wk; C = k; }
    else               { B = wv; C = v; }
    gemm_body<0>(D_MODEL, D_MODEL, blockIdx.y * 128, n0,
                 h, B + (size_t)n0 * D_MODEL, nullptr, nullptr, C);
}

// ================= TF32 flash attention ======================================
// smem: buf1/Q [0,64K): K 64x512B @0 | Vt 128x256B @32K  (Q stage: 128x512B)
//       buf0 @65536; P @131072 (8 warps x 16 rows x 256B = 32K); mask @163840
#define ATT_BUF0 65536
#define ATT_P    131072
#define ATT_MASK 163840
#define ATT_SMEM_BYTES (163840 + 512)

__device__ __forceinline__ void att_stage(
    char* smem, uint32_t sb, uint32_t bufoff,
    const float* __restrict__ Kg, const float* __restrict__ Vg,
    const int* __restrict__ bm, int kv0, int slot, int t) {
    // K tile (64 rows x 128 d fp32) via cp.async
    {
        const int row = t >> 2;
        const int seg = t & 3;
        const size_t goff = (size_t)(kv0 + row) * D_MODEL + seg * 32;
        const uint32_t rbase = sb + bufoff + (uint32_t)row * 512;
        const uint32_t swr = ((uint32_t)(row & 7)) << 4;
        #pragma unroll
        for (int i = 0; i < 8; i++)
            CP16(rbase + (((uint32_t)(seg * 128 + i * 16)) ^ swr),
                 Kg + goff + i * 4);
    }
    // Vt tile: transpose V[kv][d] -> Vt[d][kv] (128 rows x 64 fp32, 256B rows)
    {
        const int kvp = t & 31;
        const int dblk = t >> 5;
        const float* v0p = Vg + (size_t)(kv0 + 2 * kvp) * D_MODEL + dblk * 16;
        const float* v1p = v0p + D_MODEL;
        float4 a0 = *reinterpret_cast<const float4*>(v0p);
        float4 a1 = *reinterpret_cast<const float4*>(v0p + 4);
        float4 a2 = *reinterpret_cast<const float4*>(v0p + 8);
        float4 a3 = *reinterpret_cast<const float4*>(v0p + 12);
        float4 b0 = *reinterpret_cast<const float4*>(v1p);
        float4 b1 = *reinterpret_cast<const float4*>(v1p + 4);
        float4 b2 = *reinterpret_cast<const float4*>(v1p + 8);
        float4 b3 = *reinterpret_cast<const float4*>(v1p + 12);
        float va[16] = {a0.x, a0.y, a0.z, a0.w, a1.x, a1.y, a1.z, a1.w,
                        a2.x, a2.y, a2.z, a2.w, a3.x, a3.y, a3.z, a3.w};
        float vb[16] = {b0.x, b0.y, b0.z, b0.w, b1.x, b1.y, b1.z, b1.w,
                        b2.x, b2.y, b2.z, b2.w, b3.x, b3.y, b3.z, b3.w};
        const uint32_t koff = (uint32_t)(kvp * 8);
        #pragma unroll
        for (int e = 0; e < 16; e++) {
            const int d = dblk * 16 + e;
            const uint32_t addr = sb + bufoff + 32768 + (uint32_t)d * 256 +
                                  (koff ^ (((uint32_t)(d & 7)) << 4));
            STS64F(addr, va[e], vb[e]);
        }
    }
    if (t < 64)
        reinterpret_cast<int*>(smem + ATT_MASK + slot * 256)[t] = bm[kv0 + t];
}

__global__ void __launch_bounds__(256, 1)
flash_attn_tf32(const float* __restrict__ Q, const float* __restrict__ K,
                const float* __restrict__ V, const int* __restrict__ mask,
                float* __restrict__ O) {
    extern __shared__ char smem[];
    const uint32_t sb = smem_to_u32(smem);
    const int t = threadIdx.x, lane = t & 31, w = t >> 5;
    const int qi = gridDim.x - 1 - blockIdx.x;   // longest-work CTAs first
    const int h = blockIdx.y, b = blockIdx.z;
    const int q0 = qi * 128;
    const size_t base = (size_t)b * SEQ * D_MODEL + (size_t)h * HEAD_DIM;
    const int* bm = mask + b * SEQ;
    const float scale = 0.08838834764831845f;    // 1/sqrt(128)

    // ---- stage Q (128 rows x 512B, swizzled) ----
    {
        const int row = t >> 1, half = t & 1;
        const uint4* gq = reinterpret_cast<const uint4*>(
            Q + base + (size_t)(q0 + row) * D_MODEL + half * 64);
        char* qr = smem + (uint32_t)row * 512;
        const uint32_t swr = ((uint32_t)(row & 7)) << 4;
        #pragma unroll
        for (int i = 0; i < 16; i++)
            *reinterpret_cast<uint4*>(
                qr + (((uint32_t)(half * 256 + i * 16)) ^ swr)) = gq[i];
    }
    att_stage(smem, sb, ATT_BUF0, K + base, V + base, bm, 0, 0, t);
    CPCOMMIT();
    CPWAIT(0);
    __syncthreads();

    const int subrow = (lane & 7) | (((lane >> 4) & 1) << 3);
    const uint32_t klane = (uint32_t)(((lane >> 3) & 1) << 4);

    // ---- preload Q fragments (16 k8-steps) ----
    uint32_t Aq[16][4];
    {
        const int qrow = w * 16 + subrow;
        const uint32_t qsw = ((uint32_t)(qrow & 7)) << 4;
        const uint32_t qb = sb + (uint32_t)qrow * 512;
        #pragma unroll
        for (int ks = 0; ks < 16; ks++) {
            uint32_t r[4];
            ldsm_x4(qb + (((uint32_t)(ks * 32) + klane) ^ qsw), r);
            Aq[ks][0] = r[0]; Aq[ks][1] = r[2];
            Aq[ks][2] = r[1]; Aq[ks][3] = r[3];
        }
    }
    __syncthreads();

    float m1 = -1e30f, l1 = 0.f, m2 = -1e30f, l2 = 0.f;
    float acc[16][4];
    #pragma unroll
    for (int nt = 0; nt < 16; nt++)
        #pragma unroll
        for (int c = 0; c < 4; c++) acc[nt][c] = 0.f;

    const int r1g = q0 + w * 16 + (lane >> 2);
    const int r2g = r1g + 8;
    const int nch = 2 * qi + 2;
    const uint32_t sP = sb + ATT_P + (uint32_t)w * 4096;

    for (int j = 0; j < nch; j++) {
        const int s = j & 1;
        const uint32_t bufo = s ? 0u : (uint32_t)ATT_BUF0;
        const int kv0 = j * 64;

        if (j + 1 < nch) {
            att_stage(smem, sb, s ? (uint32_t)ATT_BUF0 : 0u,
                      K + base, V + base, bm, kv0 + 64, (j + 1) & 1, t);
        }
        CPCOMMIT();

        // ---- scores S = Q K^T (single-pass tf32) ----
        float sacc[8][4];
        #pragma unroll
        for (int nt = 0; nt < 8; nt++)
            #pragma unroll
            for (int c = 0; c < 4; c++) sacc[nt][c] = 0.f;

        #pragma unroll
        for (int ks = 0; ks < 16; ks++) {
            const uint32_t ko = (uint32_t)(ks * 32) + klane;
            #pragma unroll
            for (int g = 0; g < 4; g++) {
                const int kr = g * 16 + subrow;
                uint32_t r[4];
                ldsm_x4(sb + bufo + (uint32_t)kr * 512 +
                        (ko ^ (((uint32_t)(kr & 7)) << 4)), r);
                uint32_t b0[2] = {r[0], r[1]};
                uint32_t b1[2] = {r[2], r[3]};
                mma_tf32(sacc[2 * g + 0], Aq[ks], b0);
                mma_tf32(sacc[2 * g + 1], Aq[ks], b1);
            }
        }

        // ---- scale + causal + key mask ----
        const int* mrow = reinterpret_cast<const int*>(smem + ATT_MASK + s * 256);
        #pragma unroll
        for (int nt = 0; nt < 8; nt++) {
            const int c0 = nt * 8 + (lane & 3) * 2;
            const int k0g = kv0 + c0, k1g = k0g + 1;
            const bool mv0 = mrow[c0] != 0, mv1 = mrow[c0 + 1] != 0;
            float v0 = sacc[nt][0] * scale, v1 = sacc[nt][1] * scale;
            float v2 = sacc[nt][2] * scale, v3 = sacc[nt][3] * scale;
            sacc[nt][0] = (k0g > r1g || !mv0) ? -1e9f : v0;
            sacc[nt][1] = (k1g > r1g || !mv1) ? -1e9f : v1;
            sacc[nt][2] = (k0g > r2g || !mv0) ? -1e9f : v2;
            sacc[nt][3] = (k1g > r2g || !mv1) ? -1e9f : v3;
        }

        // ---- online softmax ----
        float mx1 = -1e30f, mx2 = -1e30f;
        #pragma unroll
        for (int nt = 0; nt < 8; nt++) {
            mx1 = fmaxf(mx1, fmaxf(sacc[nt][0], sacc[nt][1]));
            mx2 = fmaxf(mx2, fmaxf(sacc[nt][2], sacc[nt][3]));
        }
        mx1 = fmaxf(mx1, __shfl_xor_sync(0xFFFFFFFFu, mx1, 1));
        mx1 = fmaxf(mx1, __shfl_xor_sync(0xFFFFFFFFu, mx1, 2));
        mx2 = fmaxf(mx2, __shfl_xor_sync(0xFFFFFFFFu, mx2, 1));
        mx2 = fmaxf(mx2, __shfl_xor_sync(0xFFFFFFFFu, mx2, 2));
        const float m1n = fmaxf(m1, mx1), m2n = fmaxf(m2, mx2);
        const float a1 = __expf(m1 - m1n), a2 = __expf(m2 - m2n);
        float s1 = 0.f, s2 = 0.f;
        #pragma unroll
        for (int nt = 0; nt < 8; nt++) {
            sacc[nt][0] = __expf(sacc[nt][0] - m1n);
            sacc[nt][1] = __expf(sacc[nt][1] - m1n);
            sacc[nt][2] = __expf(sacc[nt][2] - m2n);
            sacc[nt][3] = __expf(sacc[nt][3] - m2n);
            s1 += sacc[nt][0] + sacc[nt][1];
            s2 += sacc[nt][2] + sacc[nt][3];
        }
        s1 += __shfl_xor_sync(0xFFFFFFFFu, s1, 1);
        s1 += __shfl_xor_sync(0xFFFFFFFFu, s1, 2);
        s2 += __shfl_xor_sync(0xFFFFFFFFu, s2, 1);
        s2 += __shfl_xor_sync(0xFFFFFFFFu, s2, 2);
        l1 = l1 * a1 + s1; m1 = m1n;
        l2 = l2 * a2 + s2; m2 = m2n;
        #pragma unroll
        for (int nt = 0; nt < 16; nt++) {
            acc[nt][0] *= a1; acc[nt][1] *= a1;
            acc[nt][2] *= a2; acc[nt][3] *= a2;
        }

        // ---- write P (tf32-rounded) to own smem tile, reload as A frags ----
        {
            const int lr1 = lane >> 2;
            const int lr2 = lr1 + 8;
            const uint32_t co = (uint32_t)((lane & 3) * 8);  // col*4 bytes
            const uint32_t a1b = sP + (uint32_t)lr1 * 256;
            const uint32_t a2b = sP + (uint32_t)lr2 * 256;
            const uint32_t sw1 = ((uint32_t)(lr1 & 7)) << 4;
            const uint32_t sw2 = ((uint32_t)(lr2 & 7)) << 4;
            #pragma unroll
            for (int nt = 0; nt < 8; nt++) {
                const uint32_t off = (uint32_t)(nt * 32) + co;
                STS64U(a1b + (off ^ sw1), tf32_bits(sacc[nt][0]),
                       tf32_bits(sacc[nt][1]));
                STS64U(a2b + (off ^ sw2), tf32_bits(sacc[nt][2]),
                       tf32_bits(sacc[nt][3]));
            }
        }
        __syncwarp();

        // ---- O += P V (single-pass tf32) ----
        #pragma unroll
        for (int kt = 0; kt < 8; kt++) {
            const uint32_t ko = (uint32_t)(kt * 32) + klane;
            uint32_t Pa[4];
            {
                uint32_t r[4];
                ldsm_x4(sP + (uint32_t)subrow * 256 +
                        (ko ^ (((uint32_t)(subrow & 7)) << 4)), r);
                Pa[0] = r[0]; Pa[1] = r[2]; Pa[2] = r[1]; Pa[3] = r[3];
            }
            #pragma unroll
            for (int gd = 0; gd < 8; gd++) {
                const int dr = gd * 16 + subrow;
                uint32_t r[4];
                ldsm_x4(sb + bufo + 32768 + (uint32_t)dr * 256 +
                        (ko ^ (((uint32_t)(dr & 7)) << 4)), r);
                uint32_t b0[2] = {r[0], r[1]};
                uint32_t b1[2] = {r[2], r[3]};
                mma_tf32(acc[2 * gd + 0], Pa, b0);
                mma_tf32(acc[2 * gd + 1], Pa, b1);
            }
        }

        CPWAIT(0);
        __syncthreads();
    }

    // ---- epilogue: tf32-rounded O ----
    const float i1 = (l1 > 0.f) ? 1.f / l1 : 0.f;
    const float i2 = (l2 > 0.f) ? 1.f / l2 : 0.f;
    #pragma unroll
    for (int nt = 0; nt < 16; nt++) {
        const int col = nt * 8 + (lane & 3) * 2;
        *reinterpret_cast<float2*>(O + base + (size_t)r1g * D_MODEL + col) =
            make_float2(tf32f(acc[nt][0] * i1), tf32f(acc[nt][1] * i1));
        *reinterpret_cast<float2*>(O + base + (size_t)r2g * D_MODEL + col) =
            make_float2(tf32f(acc[nt][2] * i2), tf32f(acc[nt][3] * i2));
    }
}

// ---------------- launch -----------------------------------------------------
extern "C" void kernel_launch(void* const* d_in, const int* in_sizes, int n_in,
                              void* d_out, int out_size) {
    const float* x           = (const float*)d_in[0];
    const int*   attn_mask   = (const int*)  d_in[1];
    const float* w_norm_attn = (const float*)d_in[2];
    const float* wq          = (const float*)d_in[3];
    const float* wk          = (const float*)d_in[4];
    const float* wv          = (const float*)d_in[5];
    const float* wo          = (const float*)d_in[6];
    const float* w_norm_mlp  = (const float*)d_in[7];
    const float* w_up        = (const float*)d_in[8];
    const float* w_down      = (const float*)d_in[9];
    float* out = (float*)d_out;

    float *h, *q, *k, *v, *att, *up, *x1;
    float *rwq, *rwk, *rwv, *rwo, *rwu, *rwd;
    cudaGetSymbolAddress((void**)&h, g_h);
    cudaGetSymbolAddress((void**)&q, g_q);
    cudaGetSymbolAddress((void**)&k, g_k);
    cudaGetSymbolAddress((void**)&v, g_v);
    cudaGetSymbolAddress((void**)&att, g_att);
    cudaGetSymbolAddress((void**)&up, g_up);
    cudaGetSymbolAddress((void**)&x1, g_x1);
    cudaGetSymbolAddress((void**)&rwq, g_wq);
    cudaGetSymbolAddress((void**)&rwk, g_wk);
    cudaGetSymbolAddress((void**)&rwv, g_wv);
    cudaGetSymbolAddress((void**)&rwo, g_wo);
    cudaGetSymbolAddress((void**)&rwu, g_wu);
    cudaGetSymbolAddress((void**)&rwd, g_wd);

    cudaFuncSetAttribute(flash_attn_tf32,
                         cudaFuncAttributeMaxDynamicSharedMemorySize, ATT_SMEM_BYTES);
    cudaFuncSetAttribute(qkv_gemm,
                         cudaFuncAttributeMaxDynamicSharedMemorySize, GEMM_SMEM);
    cudaFuncSetAttribute(mma_gemm<1>,
                         cudaFuncAttributeMaxDynamicSharedMemorySize, GEMM_SMEM);
    cudaFuncSetAttribute(mma_gemm<2>,
                         cudaFuncAttributeMaxDynamicSharedMemorySize, GEMM_SMEM);

    // 0) round weights to tf32 (once)
    const int DD4 = D_MODEL * D_MODEL / 4;
    const int UD4 = MLP_DIM * D_MODEL / 4;
    round_dd<<<dim3((DD4 + 255) / 256, 4), 256>>>(wq, wk, wv, wo,
                                                  rwq, rwk, rwv, rwo);
    round_ud<<<dim3((UD4 + 255) / 256, 2), 256>>>(w_up, w_down, rwu, rwd);

    // 1) rmsnorm(x) -> h (tf32-rounded)
    rmsnorm_tf32<<<TOK, 256>>>(x, w_norm_attn, h);

    // 2) fused q,k,v projection
    dim3 gQKV(3 * D_MODEL / 256, TOK / 128);
    qkv_gemm<<<gQKV, 256, GEMM_SMEM>>>(h, rwq, rwk, rwv, q, k, v);

    // 3) attention
    dim3 gA(SEQ / 128, N_HEADS, BATCH);
    flash_attn_tf32<<<gA, 256, ATT_SMEM_BYTES>>>(q, k, v, attn_mask, att);

    // 4) output projection + residual -> x1 (fp32)   [launch #6: profiled]
    dim3 gD(D_MODEL / 256, TOK / 128);
    mma_gemm<2><<<gD, 256, GEMM_SMEM>>>(D_MODEL, D_MODEL,
                                        att, rwo, x, x1, nullptr);

    // 5) rmsnorm(x1) -> h
    rmsnorm_tf32<<<TOK, 256>>>(x1, w_norm_mlp, h);

    // 6) up projection + gelu (tf32-rounded store)
    dim3 gU(MLP_DIM / 256, TOK / 128);
    mma_gemm<1><<<gU, 256, GEMM_SMEM>>>(MLP_DIM, D_MODEL,
                                        h, rwu, nullptr, nullptr, up);

    // 7) down projection + residual -> out (fp32)
    mma_gemm<2><<<gD, 256, GEMM_SMEM>>>(D_MODEL, MLP_DIM,
                                        up, rwd, x1, out, nullptr);
}

// round 10
// speedup vs baseline: 2.5839x; 2.0250x over previous
#include <cuda_runtime.h>
#include <cuda_fp16.h>
#include <math.h>
#include <stdint.h>

#define D_MODEL 2048
#define N_HEADS 16
#define HEAD_DIM 128
#define MLP_DIM 8192
#define BATCH 2
#define SEQ 2048
#define TOK (BATCH * SEQ)

typedef __half hf;

// ---------------- scratch (static device globals) ---------------------------
__device__ hf g_h[(size_t)TOK * D_MODEL];
__device__ hf g_q[(size_t)TOK * D_MODEL];
__device__ hf g_k[(size_t)TOK * D_MODEL];
__device__ hf g_v[(size_t)TOK * D_MODEL];
__device__ hf g_att[(size_t)TOK * D_MODEL];
__device__ hf g_up[(size_t)TOK * MLP_DIM];
__device__ float g_x1[(size_t)TOK * D_MODEL];
__device__ hf g_wq[(size_t)D_MODEL * D_MODEL];
__device__ hf g_wk[(size_t)D_MODEL * D_MODEL];
__device__ hf g_wv[(size_t)D_MODEL * D_MODEL];
__device__ hf g_wo[(size_t)D_MODEL * D_MODEL];
__device__ hf g_wu[(size_t)MLP_DIM * D_MODEL];
__device__ hf g_wd[(size_t)D_MODEL * MLP_DIM];

// ================= PTX helpers (baseline PTX, sm_80+) =======================
__device__ __forceinline__ uint32_t smem_to_u32(const void* p) {
    uint32_t a;
    asm("{ .reg .u64 t; cvta.to.shared.u64 t, %1; cvt.u32.u64 %0, t; }"
        : "=r"(a) : "l"(p));
    return a;
}
__device__ __forceinline__ void ldsm_x4(uint32_t addr, uint32_t* r) {
    asm volatile("ldmatrix.sync.aligned.m8n8.x4.shared.b16 {%0,%1,%2,%3}, [%4];"
                 : "=r"(r[0]), "=r"(r[1]), "=r"(r[2]), "=r"(r[3]) : "r"(addr));
}
__device__ __forceinline__ void mma_f16(float* d, const uint32_t* a,
                                        const uint32_t* b) {
    asm volatile(
        "mma.sync.aligned.m16n8k16.row.col.f32.f16.f16.f32 "
        "{%0,%1,%2,%3}, {%4,%5,%6,%7}, {%8,%9}, {%0,%1,%2,%3};"
        : "+f"(d[0]), "+f"(d[1]), "+f"(d[2]), "+f"(d[3])
        : "r"(a[0]), "r"(a[1]), "r"(a[2]), "r"(a[3]), "r"(b[0]), "r"(b[1]));
}
__device__ __forceinline__ uint32_t h2_bits(__half2 v) {
    return *reinterpret_cast<uint32_t*>(&v);
}
#define CP16(dst, src) \
    asm volatile("cp.async.cg.shared.global [%0], [%1], 16;" \
                 :: "r"(dst), "l"(src) : "memory")
#define CPCOMMIT() asm volatile("cp.async.commit_group;" ::: "memory")
#define CPWAIT(n)  asm volatile("cp.async.wait_group %0;" :: "n"(n) : "memory")

// ================= weight rounding fp32 -> fp16 (once) =======================
__device__ __forceinline__ void round_store(const float* src, hf* dst, int i) {
    float4 v = reinterpret_cast<const float4*>(src)[i];
    __half2 a = __floats2half2_rn(v.x, v.y);
    __half2 b = __floats2half2_rn(v.z, v.w);
    reinterpret_cast<uint2*>(dst)[i] = make_uint2(h2_bits(a), h2_bits(b));
}
__global__ void round_dd(const float* __restrict__ wq, const float* __restrict__ wk,
                         const float* __restrict__ wv, const float* __restrict__ wo,
                         hf* oq, hf* ok, hf* ov, hf* oo) {
    int i = blockIdx.x * blockDim.x + threadIdx.x;
    if (i >= D_MODEL * D_MODEL / 4) return;
    switch (blockIdx.y) {
        case 0: round_store(wq, oq, i); break;
        case 1: round_store(wk, ok, i); break;
        case 2: round_store(wv, ov, i); break;
        default: round_store(wo, oo, i); break;
    }
}
__global__ void round_ud(const float* __restrict__ wu, const float* __restrict__ wd,
                         hf* ou, hf* od) {
    int i = blockIdx.x * blockDim.x + threadIdx.x;
    if (i >= MLP_DIM * D_MODEL / 4) return;
    if (blockIdx.y == 0) round_store(wu, ou, i);
    else                 round_store(wd, od, i);
}

// ================= RMSNorm -> fp16 ===========================================
__global__ void rmsnorm_h(const float* __restrict__ x,
                          const float* __restrict__ w,
                          hf* __restrict__ out) {
    int row = blockIdx.x;
    const float4* xr = reinterpret_cast<const float4*>(x + (size_t)row * D_MODEL);
    const float4* w4 = reinterpret_cast<const float4*>(w);

    float ss = 0.f;
    for (int i = threadIdx.x; i < D_MODEL / 4; i += blockDim.x) {
        float4 v = xr[i];
        ss += v.x * v.x + v.y * v.y + v.z * v.z + v.w * v.w;
    }
    for (int off = 16; off > 0; off >>= 1)
        ss += __shfl_xor_sync(0xFFFFFFFFu, ss, off);
    __shared__ float red[8];
    __shared__ float s_rms;
    int lane = threadIdx.x & 31, wid = threadIdx.x >> 5;
    if (lane == 0) red[wid] = ss;
    __syncthreads();
    if (threadIdx.x == 0) {
        float tt = 0.f;
        #pragma unroll
        for (int i = 0; i < 8; i++) tt += red[i];
        s_rms = rsqrtf(tt / (float)D_MODEL + 1e-6f);
    }
    __syncthreads();
    float r = s_rms;
    uint2* o2 = reinterpret_cast<uint2*>(out + (size_t)row * D_MODEL);
    for (int i = threadIdx.x; i < D_MODEL / 4; i += blockDim.x) {
        float4 v = xr[i];
        float4 ww = w4[i];
        __half2 a = __floats2half2_rn(v.x * r * ww.x, v.y * r * ww.y);
        __half2 b = __floats2half2_rn(v.z * r * ww.z, v.w * r * ww.w);
        o2[i] = make_uint2(h2_bits(a), h2_bits(b));
    }
}

// ================= FP16 GEMM: 128x256 CTA, 64x64 warp, KC=64 halves ==========
// C = A @ B^T (A,B fp16 row-major ld K; fp32 accumulate)
// EPI: 0 = fp16 store, 1 = gelu + fp16 store, 2 = residual fp32
#define KC 64
#define ROWB 128
#define A_TILE 16384            // 128 rows x 128B
#define B_TILE 32768            // 256 rows x 128B
#define STAGE_B (A_TILE + B_TILE)
#define NSTAGE 4
#define GEMM_SMEM (NSTAGE * STAGE_B)   // 192 KB

template <int EPI>
__device__ __forceinline__ void gemm_body(
    int Nc, int K, int m0, int c0,
    const hf* __restrict__ A, const hf* __restrict__ B,  // B pre-offset
    const float* __restrict__ RES, float* __restrict__ Cf,
    hf* __restrict__ Ch) {
    extern __shared__ char smem[];
    const uint32_t su = smem_to_u32(smem);

    const int t = threadIdx.x;
    const int lane = t & 31;
    const int wid = t >> 5;
    const int wm = wid & 1;
    const int wn = wid >> 1;

    // A staging: row = t>>1, half-of-row = t&1 (64B each); 4 CP16
    const int arow = t >> 1;
    const int ahalf = t & 1;
    const hf* Asrc = A + (size_t)(m0 + arow) * K + ahalf * 32;
    const uint32_t asw = ((uint32_t)(arow & 7)) << 4;
    const uint32_t adst = (uint32_t)arow * ROWB;

    // B staging: row = t (128B); 8 CP16
    const hf* Bsrc = B + (size_t)t * K;
    const uint32_t bsw = ((uint32_t)(t & 7)) << 4;
    const uint32_t bdst = (uint32_t)A_TILE + (uint32_t)t * ROWB;

    auto CP_chunk = [&](int s, int k0) {
        const uint32_t st = su + (uint32_t)s * STAGE_B;
        #pragma unroll
        for (int c = 0; c < 4; c++)
            CP16(st + adst + (((uint32_t)(ahalf * 64 + c * 16)) ^ asw),
                 Asrc + k0 + c * 8);
        #pragma unroll
        for (int c = 0; c < 8; c++)
            CP16(st + bdst + (((uint32_t)(c * 16)) ^ bsw), Bsrc + k0 + c * 8);
    };

    float acc[4][8][4];
    #pragma unroll
    for (int mt = 0; mt < 4; mt++)
        #pragma unroll
        for (int nt = 0; nt < 8; nt++)
            #pragma unroll
            for (int j = 0; j < 4; j++) acc[mt][nt][j] = 0.f;

    const int nch = K / KC;
    #pragma unroll
    for (int s = 0; s < NSTAGE - 1; s++) {
        CP_chunk(s, s * KC);
        CPCOMMIT();
    }

    const int lrow16 = lane & 15;
    const int cg = (lane >> 4) & 1;

    for (int i = 0; i < nch; i++) {
        CPWAIT(NSTAGE - 2);
        __syncthreads();

        const uint32_t st = su + (uint32_t)(i % NSTAGE) * STAGE_B;

        #pragma unroll
        for (int ks = 0; ks < 4; ks++) {
            const uint32_t cbh = (uint32_t)(ks * 32 + cg * 16);
            uint32_t Af[4][4];
            #pragma unroll
            for (int mt = 0; mt < 4; mt++) {
                const int row = wm * 64 + mt * 16 + lrow16;
                const uint32_t swz = (uint32_t)(row & 7) << 4;
                ldsm_x4(st + (uint32_t)row * ROWB + (cbh ^ swz), Af[mt]);
            }
            #pragma unroll
            for (int q = 0; q < 4; q++) {
                const int row = wn * 64 + q * 16 + lrow16;
                const uint32_t swz = (uint32_t)(row & 7) << 4;
                uint32_t r[4];
                ldsm_x4(st + A_TILE + (uint32_t)row * ROWB + (cbh ^ swz), r);
                uint32_t b0[2] = {r[0], r[2]};
                uint32_t b1[2] = {r[1], r[3]};
                #pragma unroll
                for (int mt = 0; mt < 4; mt++) {
                    mma_f16(acc[mt][2 * q + 0], Af[mt], b0);
                    mma_f16(acc[mt][2 * q + 1], Af[mt], b1);
                }
            }
        }

        if (i + NSTAGE - 1 < nch)
            CP_chunk((i + NSTAGE - 1) % NSTAGE, (i + NSTAGE - 1) * KC);
        CPCOMMIT();
    }

    // ---- epilogue ----
    const int er0 = m0 + wm * 64 + (lane >> 2);
    const int ec0 = c0 + wn * 64 + (lane & 3) * 2;
    #pragma unroll
    for (int mt = 0; mt < 4; mt++) {
        #pragma unroll
        for (int g = 0; g < 2; g++) {
            const int row = er0 + mt * 16 + g * 8;
            #pragma unroll
            for (int nt = 0; nt < 8; nt++) {
                const int col = ec0 + nt * 8;
                float v0 = acc[mt][nt][g * 2 + 0];
                float v1 = acc[mt][nt][g * 2 + 1];
                size_t roff = (size_t)row * Nc + col;
                if (EPI == 2) {
                    float2 r = *reinterpret_cast<const float2*>(RES + roff);
                    *reinterpret_cast<float2*>(Cf + roff) =
                        make_float2(v0 + r.x, v1 + r.y);
                } else {
                    if (EPI == 1) {
                        v0 = 0.5f * v0 * (1.0f + erff(v0 * 0.70710678118654752f));
                        v1 = 0.5f * v1 * (1.0f + erff(v1 * 0.70710678118654752f));
                    }
                    *reinterpret_cast<uint32_t*>(Ch + roff) =
                        h2_bits(__floats2half2_rn(v0, v1));
                }
            }
        }
    }
}

template <int EPI>
__global__ void __launch_bounds__(256, 1)
mma_gemm(int N, int K,
         const hf* __restrict__ A, const hf* __restrict__ B,
         const float* __restrict__ RES, float* __restrict__ Cf,
         hf* __restrict__ Ch) {
    const int n0 = blockIdx.x * 256;
    gemm_body<EPI>(N, K, blockIdx.y * 128, n0, A, B + (size_t)n0 * K,
                   RES, Cf, Ch);
}

// Fused QKV
__global__ void __launch_bounds__(256, 1)
qkv_gemm(const hf* __restrict__ h,
         const hf* __restrict__ wq, const hf* __restrict__ wk,
         const hf* __restrict__ wv,
         hf* __restrict__ q, hf* __restrict__ k, hf* __restrict__ v) {
    const int n0g = blockIdx.x * 256;
    const int sel = n0g >> 11;
    const int n0 = n0g & 2047;
    const hf* B;
    hf* C;
    if (sel == 0)      { B = wq; C = q; }
    else if (sel == 1) { B = wk; C = k; }
    else               { B = wv; C = v; }
    gemm_body<0>(D_MODEL, D_MODEL, blockIdx.y * 128, n0,
                 h, B + (size_t)n0 * D_MODEL, nullptr, nullptr, C);
}

// ================= FP16 flash attention ======================================
// smem: buf1/Q @0 (32KB: K 64x256B @0 | Vt 128x128B @16K), buf0 @32768,
//       mask @65536 (+512). Q staging: 128 rows x 256B over buf1 region.
#define ATT_BUF0 32768
#define ATT_MASK 65536
#define ATT_SMEM_BYTES (65536 + 512)

__device__ __forceinline__ void att_stage(
    char* smem, uint32_t sb, uint32_t bufoff,
    const hf* __restrict__ Kg, const hf* __restrict__ Vg,
    const int* __restrict__ bm, int kv0, int slot, int t) {
    // K tile (64 kv-rows x 128 d halves = 256B rows) via cp.async
    {
        const int row = t >> 2;
        const int dq = (t & 3) * 32;
        const size_t goff = (size_t)(kv0 + row) * D_MODEL + dq;
        const uint32_t rbase = sb + bufoff + (uint32_t)row * 256;
        const uint32_t swr = ((uint32_t)(row & 7)) << 4;
        #pragma unroll
        for (int i = 0; i < 4; i++)
            CP16(rbase + (((uint32_t)(dq * 2 + i * 16)) ^ swr),
                 Kg + goff + i * 8);
    }
    // Vt tile: transpose V[kv][d] -> Vt[d][kv] (128 d-rows x 64 kv = 128B rows)
    {
        const int kvp = t & 31;
        const int dblk = t >> 5;
        const size_t r0 = (size_t)(kv0 + 2 * kvp) * D_MODEL + dblk * 16;
        const size_t r1 = r0 + D_MODEL;
        uint4 h0a = *reinterpret_cast<const uint4*>(Vg + r0);
        uint4 h0b = *reinterpret_cast<const uint4*>(Vg + r0 + 8);
        uint4 h1a = *reinterpret_cast<const uint4*>(Vg + r1);
        uint4 h1b = *reinterpret_cast<const uint4*>(Vg + r1 + 8);
        uint32_t h0[8] = {h0a.x, h0a.y, h0a.z, h0a.w, h0b.x, h0b.y, h0b.z, h0b.w};
        uint32_t h1[8] = {h1a.x, h1a.y, h1a.z, h1a.w, h1b.x, h1b.y, h1b.z, h1b.w};
        const uint32_t koff = (uint32_t)(kvp * 4);
        #pragma unroll
        for (int dd = 0; dd < 8; dd++) {
            const int d0 = dblk * 16 + dd * 2;
            const uint32_t vb0 = sb + bufoff + 16384 + (uint32_t)d0 * 128 +
                                 (koff ^ ((uint32_t)(d0 & 7) << 4));
            const uint32_t vb1 = sb + bufoff + 16384 + (uint32_t)(d0 + 1) * 128 +
                                 (koff ^ ((uint32_t)((d0 + 1) & 7) << 4));
            asm volatile("st.shared.b32 [%0], %1;" :: "r"(vb0),
                         "r"(__byte_perm(h0[dd], h1[dd], 0x5410)) : "memory");
            asm volatile("st.shared.b32 [%0], %1;" :: "r"(vb1),
                         "r"(__byte_perm(h0[dd], h1[dd], 0x7632)) : "memory");
        }
    }
    if (t < 64)
        reinterpret_cast<int*>(smem + ATT_MASK + slot * 256)[t] = bm[kv0 + t];
}

__global__ void __launch_bounds__(256, 1)
flash_attn_h(const hf* __restrict__ Q, const hf* __restrict__ K,
             const hf* __restrict__ V, const int* __restrict__ mask,
             hf* __restrict__ O) {
    extern __shared__ char smem[];
    const uint32_t sb = smem_to_u32(smem);
    const int t = threadIdx.x, lane = t & 31, w = t >> 5;
    const int qi = gridDim.x - 1 - blockIdx.x;   // longest-work CTAs first
    const int h = blockIdx.y, b = blockIdx.z;
    const int q0 = qi * 128;
    const size_t base = (size_t)b * SEQ * D_MODEL + (size_t)h * HEAD_DIM;
    const int* bm = mask + b * SEQ;
    const float scale = 0.08838834764831845f;    // 1/sqrt(128)

    // ---- stage Q (128 rows x 256B, swizzled) into buf1 region ----
    {
        const int row = t >> 1, half = t & 1;
        const uint4* gq = reinterpret_cast<const uint4*>(
            Q + base + (size_t)(q0 + row) * D_MODEL + half * 64);
        char* qr = smem + (uint32_t)row * 256;
        const uint32_t swr = ((uint32_t)(row & 7)) << 4;
        #pragma unroll
        for (int i = 0; i < 8; i++)
            *reinterpret_cast<uint4*>(
                qr + (((uint32_t)(half * 128 + i * 16)) ^ swr)) = gq[i];
    }
    att_stage(smem, sb, ATT_BUF0, K + base, V + base, bm, 0, 0, t);
    CPCOMMIT();
    CPWAIT(0);
    __syncthreads();

    // ---- preload Q fragments (8 k16 steps over d=128) ----
    uint32_t Aq[8][4];
    {
        const int r = w * 16 + (lane & 15);
        const uint32_t swz = ((uint32_t)(r & 7)) << 4;
        const uint32_t cgo = ((uint32_t)(lane >> 4)) << 4;
        const uint32_t qb = sb + (uint32_t)r * 256;
        #pragma unroll
        for (int ds = 0; ds < 8; ds++)
            ldsm_x4(qb + (((uint32_t)(ds * 32)) + cgo) ^ swz
                        ? (qb + ((((uint32_t)(ds * 32)) + cgo) ^ swz)) : qb, Aq[ds]);
    }
    __syncthreads();

    float m1 = -1e30f, l1 = 0.f, m2 = -1e30f, l2 = 0.f;
    float acc[16][4];
    #pragma unroll
    for (int nt = 0; nt < 16; nt++)
        #pragma unroll
        for (int c = 0; c < 4; c++) acc[nt][c] = 0.f;

    const int r1g = q0 + w * 16 + (lane >> 2);
    const int r2g = r1g + 8;
    const int nch = 2 * qi + 2;
    const uint32_t cgo = ((uint32_t)(lane >> 4)) << 4;

    for (int j = 0; j < nch; j++) {
        const int s = j & 1;
        const uint32_t bufo = s ? 0u : (uint32_t)ATT_BUF0;
        const int kv0 = j * 64;

        if (j + 1 < nch) {
            att_stage(smem, sb, s ? (uint32_t)ATT_BUF0 : 0u,
                      K + base, V + base, bm, kv0 + 64, (j + 1) & 1, t);
        }
        CPCOMMIT();

        // ---- scores S = Q K^T ----
        float sacc[8][4];
        #pragma unroll
        for (int nt = 0; nt < 8; nt++)
            #pragma unroll
            for (int c = 0; c < 4; c++) sacc[nt][c] = 0.f;

        #pragma unroll
        for (int g4 = 0; g4 < 4; g4++) {
            const int kr = g4 * 16 + (lane & 15);
            const uint32_t swz = ((uint32_t)(kr & 7)) << 4;
            const uint32_t kb = sb + bufo + (uint32_t)kr * 256;
            #pragma unroll
            for (int ds = 0; ds < 8; ds++) {
                uint32_t r[4];
                ldsm_x4(kb + ((((uint32_t)(ds * 32)) + cgo) ^ swz), r);
                uint32_t b0[2] = {r[0], r[2]};
                uint32_t b1[2] = {r[1], r[3]};
                mma_f16(sacc[2 * g4 + 0], Aq[ds], b0);
                mma_f16(sacc[2 * g4 + 1], Aq[ds], b1);
            }
        }

        // ---- scale + causal + key mask ----
        const int* mrow = reinterpret_cast<const int*>(smem + ATT_MASK + s * 256);
        #pragma unroll
        for (int nt = 0; nt < 8; nt++) {
            const int c0 = nt * 8 + (lane & 3) * 2;
            const int k0g = kv0 + c0, k1g = k0g + 1;
            const bool mv0 = mrow[c0] != 0, mv1 = mrow[c0 + 1] != 0;
            float v0 = sacc[nt][0] * scale, v1 = sacc[nt][1] * scale;
            float v2 = sacc[nt][2] * scale, v3 = sacc[nt][3] * scale;
            sacc[nt][0] = (k0g > r1g || !mv0) ? -1e9f : v0;
            sacc[nt][1] = (k1g > r1g || !mv1) ? -1e9f : v1;
            sacc[nt][2] = (k0g > r2g || !mv0) ? -1e9f : v2;
            sacc[nt][3] = (k1g > r2g || !mv1) ? -1e9f : v3;
        }

        // ---- online softmax ----
        float mx1 = -1e30f, mx2 = -1e30f;
        #pragma unroll
        for (int nt = 0; nt < 8; nt++) {
            mx1 = fmaxf(mx1, fmaxf(sacc[nt][0], sacc[nt][1]));
            mx2 = fmaxf(mx2, fmaxf(sacc[nt][2], sacc[nt][3]));
        }
        mx1 = fmaxf(mx1, __shfl_xor_sync(0xFFFFFFFFu, mx1, 1));
        mx1 = fmaxf(mx1, __shfl_xor_sync(0xFFFFFFFFu, mx1, 2));
        mx2 = fmaxf(mx2, __shfl_xor_sync(0xFFFFFFFFu, mx2, 1));
        mx2 = fmaxf(mx2, __shfl_xor_sync(0xFFFFFFFFu, mx2, 2));
        const float m1n = fmaxf(m1, mx1), m2n = fmaxf(m2, mx2);
        const float a1 = __expf(m1 - m1n), a2 = __expf(m2 - m2n);
        float s1 = 0.f, s2 = 0.f;
        #pragma unroll
        for (int nt = 0; nt < 8; nt++) {
            sacc[nt][0] = __expf(sacc[nt][0] - m1n);
            sacc[nt][1] = __expf(sacc[nt][1] - m1n);
            sacc[nt][2] = __expf(sacc[nt][2] - m2n);
            sacc[nt][3] = __expf(sacc[nt][3] - m2n);
            s1 += sacc[nt][0] + sacc[nt][1];
            s2 += sacc[nt][2] + sacc[nt][3];
        }
        s1 += __shfl_xor_sync(0xFFFFFFFFu, s1, 1);
        s1 += __shfl_xor_sync(0xFFFFFFFFu, s1, 2);
        s2 += __shfl_xor_sync(0xFFFFFFFFu, s2, 1);
        s2 += __shfl_xor_sync(0xFFFFFFFFu, s2, 2);
        l1 = l1 * a1 + s1; m1 = m1n;
        l2 = l2 * a2 + s2; m2 = m2n;
        #pragma unroll
        for (int nt = 0; nt < 16; nt++) {
            acc[nt][0] *= a1; acc[nt][1] *= a1;
            acc[nt][2] *= a2; acc[nt][3] *= a2;
        }

        // ---- O += P V (P built in registers as fp16 A-fragments) ----
        #pragma unroll
        for (int ks = 0; ks < 4; ks++) {
            const float* p0 = sacc[2 * ks];
            const float* p1 = sacc[2 * ks + 1];
            uint32_t pa[4];
            pa[0] = h2_bits(__floats2half2_rn(p0[0], p0[1]));
            pa[1] = h2_bits(__floats2half2_rn(p0[2], p0[3]));
            pa[2] = h2_bits(__floats2half2_rn(p1[0], p1[1]));
            pa[3] = h2_bits(__floats2half2_rn(p1[2], p1[3]));

            #pragma unroll
            for (int gd = 0; gd < 8; gd++) {
                const int dr = gd * 16 + (lane & 15);
                const uint32_t swz = ((uint32_t)(dr & 7)) << 4;
                const uint32_t vb = sb + bufo + 16384 + (uint32_t)dr * 128;
                uint32_t r[4];
                ldsm_x4(vb + ((((uint32_t)(ks * 32)) + cgo) ^ swz), r);
                uint32_t b0[2] = {r[0], r[2]};
                uint32_t b1[2] = {r[1], r[3]};
                mma_f16(acc[2 * gd + 0], pa, b0);
                mma_f16(acc[2 * gd + 1], pa, b1);
            }
        }

        CPWAIT(0);
        __syncthreads();
    }

    // ---- epilogue: fp16 O ----
    const float i1 = (l1 > 0.f) ? 1.f / l1 : 0.f;
    const float i2 = (l2 > 0.f) ? 1.f / l2 : 0.f;
    #pragma unroll
    for (int nt = 0; nt < 16; nt++) {
        const int col = nt * 8 + (lane & 3) * 2;
        *reinterpret_cast<uint32_t*>(O + base + (size_t)r1g * D_MODEL + col) =
            h2_bits(__floats2half2_rn(acc[nt][0] * i1, acc[nt][1] * i1));
        *reinterpret_cast<uint32_t*>(O + base + (size_t)r2g * D_MODEL + col) =
            h2_bits(__floats2half2_rn(acc[nt][2] * i2, acc[nt][3] * i2));
    }
}

// ---------------- launch -----------------------------------------------------
extern "C" void kernel_launch(void* const* d_in, const int* in_sizes, int n_in,
                              void* d_out, int out_size) {
    const float* x           = (const float*)d_in[0];
    const int*   attn_mask   = (const int*)  d_in[1];
    const float* w_norm_attn = (const float*)d_in[2];
    const float* wq          = (const float*)d_in[3];
    const float* wk          = (const float*)d_in[4];
    const float* wv          = (const float*)d_in[5];
    const float* wo          = (const float*)d_in[6];
    const float* w_norm_mlp  = (const float*)d_in[7];
    const float* w_up        = (const float*)d_in[8];
    const float* w_down      = (const float*)d_in[9];
    float* out = (float*)d_out;

    hf *h, *q, *k, *v, *att, *up;
    hf *rwq, *rwk, *rwv, *rwo, *rwu, *rwd;
    float* x1;
    cudaGetSymbolAddress((void**)&h, g_h);
    cudaGetSymbolAddress((void**)&q, g_q);
    cudaGetSymbolAddress((void**)&k, g_k);
    cudaGetSymbolAddress((void**)&v, g_v);
    cudaGetSymbolAddress((void**)&att, g_att);
    cudaGetSymbolAddress((void**)&up, g_up);
    cudaGetSymbolAddress((void**)&x1, g_x1);
    cudaGetSymbolAddress((void**)&rwq, g_wq);
    cudaGetSymbolAddress((void**)&rwk, g_wk);
    cudaGetSymbolAddress((void**)&rwv, g_wv);
    cudaGetSymbolAddress((void**)&rwo, g_wo);
    cudaGetSymbolAddress((void**)&rwu, g_wu);
    cudaGetSymbolAddress((void**)&rwd, g_wd);

    cudaFuncSetAttribute(flash_attn_h,
                         cudaFuncAttributeMaxDynamicSharedMemorySize, ATT_SMEM_BYTES);
    cudaFuncSetAttribute(qkv_gemm,
                         cudaFuncAttributeMaxDynamicSharedMemorySize, GEMM_SMEM);
    cudaFuncSetAttribute(mma_gemm<1>,
                         cudaFuncAttributeMaxDynamicSharedMemorySize, GEMM_SMEM);
    cudaFuncSetAttribute(mma_gemm<2>,
                         cudaFuncAttributeMaxDynamicSharedMemorySize, GEMM_SMEM);

    // 0) round weights to fp16 (once)
    const int DD4 = D_MODEL * D_MODEL / 4;
    const int UD4 = MLP_DIM * D_MODEL / 4;
    round_dd<<<dim3((DD4 + 255) / 256, 4), 256>>>(wq, wk, wv, wo,
                                                  rwq, rwk, rwv, rwo);
    round_ud<<<dim3((UD4 + 255) / 256, 2), 256>>>(w_up, w_down, rwu, rwd);

    // 1) rmsnorm(x) -> h (fp16)
    rmsnorm_h<<<TOK, 256>>>(x, w_norm_attn, h);

    // 2) fused q,k,v projection
    dim3 gQKV(3 * D_MODEL / 256, TOK / 128);
    qkv_gemm<<<gQKV, 256, GEMM_SMEM>>>(h, rwq, rwk, rwv, q, k, v);

    // 3) attention
    dim3 gA(SEQ / 128, N_HEADS, BATCH);
    flash_attn_h<<<gA, 256, ATT_SMEM_BYTES>>>(q, k, v, attn_mask, att);

    // 4) output projection + residual -> x1 (fp32)   [launch #6: profiled]
    dim3 gD(D_MODEL / 256, TOK / 128);
    mma_gemm<2><<<gD, 256, GEMM_SMEM>>>(D_MODEL, D_MODEL,
                                        att, rwo, x, x1, nullptr);

    // 5) rmsnorm(x1) -> h
    rmsnorm_h<<<TOK, 256>>>(x1, w_norm_mlp, h);

    // 6) up projection + gelu (fp16 store)
    dim3 gU(MLP_DIM / 256, TOK / 128);
    mma_gemm<1><<<gU, 256, GEMM_SMEM>>>(MLP_DIM, D_MODEL,
                                        h, rwu, nullptr, nullptr, up);

    // 7) down projection + residual -> out (fp32)
    mma_gemm<2><<<gD, 256, GEMM_SMEM>>>(D_MODEL, MLP_DIM,
                                        up, rwd, x1, out, nullptr);
}

// round 11
// speedup vs baseline: 3.4266x; 1.3261x over previous
#include <cuda_runtime.h>
#include <cuda_fp16.h>
#include <math.h>
#include <stdint.h>

#define D_MODEL 2048
#define N_HEADS 16
#define HEAD_DIM 128
#define MLP_DIM 8192
#define BATCH 2
#define SEQ 2048
#define TOK (BATCH * SEQ)

typedef __half hf;

// ---------------- scratch (static device globals) ---------------------------
__device__ hf g_h[(size_t)TOK * D_MODEL];
__device__ hf g_q[(size_t)TOK * D_MODEL];
__device__ hf g_k[(size_t)TOK * D_MODEL];
__device__ hf g_v[(size_t)TOK * D_MODEL];
__device__ hf g_att[(size_t)TOK * D_MODEL];
__device__ hf g_up[(size_t)TOK * MLP_DIM];
__device__ float g_x1[(size_t)TOK * D_MODEL];
__device__ hf g_wq[(size_t)D_MODEL * D_MODEL];
__device__ hf g_wk[(size_t)D_MODEL * D_MODEL];
__device__ hf g_wv[(size_t)D_MODEL * D_MODEL];
__device__ hf g_wo[(size_t)D_MODEL * D_MODEL];
__device__ hf g_wu[(size_t)MLP_DIM * D_MODEL];
__device__ hf g_wd[(size_t)D_MODEL * MLP_DIM];

// ================= PTX helpers (baseline PTX, sm_80+) =======================
__device__ __forceinline__ uint32_t smem_to_u32(const void* p) {
    uint32_t a;
    asm("{ .reg .u64 t; cvta.to.shared.u64 t, %1; cvt.u32.u64 %0, t; }"
        : "=r"(a) : "l"(p));
    return a;
}
__device__ __forceinline__ void ldsm_x4(uint32_t addr, uint32_t* r) {
    asm volatile("ldmatrix.sync.aligned.m8n8.x4.shared.b16 {%0,%1,%2,%3}, [%4];"
                 : "=r"(r[0]), "=r"(r[1]), "=r"(r[2]), "=r"(r[3]) : "r"(addr));
}
__device__ __forceinline__ void mma_f16(float* d, const uint32_t* a,
                                        const uint32_t* b) {
    asm volatile(
        "mma.sync.aligned.m16n8k16.row.col.f32.f16.f16.f32 "
        "{%0,%1,%2,%3}, {%4,%5,%6,%7}, {%8,%9}, {%0,%1,%2,%3};"
        : "+f"(d[0]), "+f"(d[1]), "+f"(d[2]), "+f"(d[3])
        : "r"(a[0]), "r"(a[1]), "r"(a[2]), "r"(a[3]), "r"(b[0]), "r"(b[1]));
}
__device__ __forceinline__ uint32_t h2_bits(__half2 v) {
    return *reinterpret_cast<uint32_t*>(&v);
}
#define CP16(dst, src) \
    asm volatile("cp.async.cg.shared.global [%0], [%1], 16;" \
                 :: "r"(dst), "l"(src) : "memory")
#define CPCOMMIT() asm volatile("cp.async.commit_group;" ::: "memory")
#define CPWAIT(n)  asm volatile("cp.async.wait_group %0;" :: "n"(n) : "memory")

// ================= weight rounding fp32 -> fp16 (once) =======================
__device__ __forceinline__ void round_store(const float* src, hf* dst, int i) {
    float4 v = reinterpret_cast<const float4*>(src)[i];
    __half2 a = __floats2half2_rn(v.x, v.y);
    __half2 b = __floats2half2_rn(v.z, v.w);
    reinterpret_cast<uint2*>(dst)[i] = make_uint2(h2_bits(a), h2_bits(b));
}
__global__ void round_dd(const float* __restrict__ wq, const float* __restrict__ wk,
                         const float* __restrict__ wv, const float* __restrict__ wo,
                         hf* oq, hf* ok, hf* ov, hf* oo) {
    int i = blockIdx.x * blockDim.x + threadIdx.x;
    if (i >= D_MODEL * D_MODEL / 4) return;
    switch (blockIdx.y) {
        case 0: round_store(wq, oq, i); break;
        case 1: round_store(wk, ok, i); break;
        case 2: round_store(wv, ov, i); break;
        default: round_store(wo, oo, i); break;
    }
}
__global__ void round_ud(const float* __restrict__ wu, const float* __restrict__ wd,
                         hf* ou, hf* od) {
    int i = blockIdx.x * blockDim.x + threadIdx.x;
    if (i >= MLP_DIM * D_MODEL / 4) return;
    if (blockIdx.y == 0) round_store(wu, ou, i);
    else                 round_store(wd, od, i);
}

// ================= RMSNorm -> fp16 ===========================================
__global__ void rmsnorm_h(const float* __restrict__ x,
                          const float* __restrict__ w,
                          hf* __restrict__ out) {
    int row = blockIdx.x;
    const float4* xr = reinterpret_cast<const float4*>(x + (size_t)row * D_MODEL);
    const float4* w4 = reinterpret_cast<const float4*>(w);

    float ss = 0.f;
    for (int i = threadIdx.x; i < D_MODEL / 4; i += blockDim.x) {
        float4 v = xr[i];
        ss += v.x * v.x + v.y * v.y + v.z * v.z + v.w * v.w;
    }
    for (int off = 16; off > 0; off >>= 1)
        ss += __shfl_xor_sync(0xFFFFFFFFu, ss, off);
    __shared__ float red[8];
    __shared__ float s_rms;
    int lane = threadIdx.x & 31, wid = threadIdx.x >> 5;
    if (lane == 0) red[wid] = ss;
    __syncthreads();
    if (threadIdx.x == 0) {
        float tt = 0.f;
        #pragma unroll
        for (int i = 0; i < 8; i++) tt += red[i];
        s_rms = rsqrtf(tt / (float)D_MODEL + 1e-6f);
    }
    __syncthreads();
    float r = s_rms;
    uint2* o2 = reinterpret_cast<uint2*>(out + (size_t)row * D_MODEL);
    for (int i = threadIdx.x; i < D_MODEL / 4; i += blockDim.x) {
        float4 v = xr[i];
        float4 ww = w4[i];
        __half2 a = __floats2half2_rn(v.x * r * ww.x, v.y * r * ww.y);
        __half2 b = __floats2half2_rn(v.z * r * ww.z, v.w * r * ww.w);
        o2[i] = make_uint2(h2_bits(a), h2_bits(b));
    }
}

// ================= FP16 GEMM: 128x256 CTA, 512 thr, 32x64 warp tile ==========
// C = A @ B^T (fp16 in, fp32 accumulate)
// EPI: 0 = fp16 store, 1 = gelu + fp16 store, 2 = residual fp32
#define KC 64
#define ROWB 128
#define A_TILE 16384            // 128 rows x 128B
#define B_TILE 32768            // 256 rows x 128B
#define STAGE_B (A_TILE + B_TILE)
#define NSTAGE 4
#define GEMM_SMEM (NSTAGE * STAGE_B)   // 192 KB
#define GTHREADS 512

template <int EPI>
__device__ __forceinline__ void gemm_body(
    int Nc, int K, int m0, int c0,
    const hf* __restrict__ A, const hf* __restrict__ B,  // B pre-offset
    const float* __restrict__ RES, float* __restrict__ Cf,
    hf* __restrict__ Ch) {
    extern __shared__ char smem[];
    const uint32_t su = smem_to_u32(smem);

    const int t = threadIdx.x;
    const int lane = t & 31;
    const int wid = t >> 5;        // 0..15
    const int wm = wid & 3;        // 4 m-warps x 32 rows
    const int wn = wid >> 2;       // 4 n-warps x 64 cols

    // A staging: row = t>>2, seg = t&3 (32B each); 2 CP16 per thread
    const int arow = t >> 2;
    const int aseg = t & 3;
    const hf* Asrc = A + (size_t)(m0 + arow) * K + aseg * 16;
    const uint32_t asw = ((uint32_t)(arow & 7)) << 4;
    const uint32_t adst = (uint32_t)arow * ROWB;

    // B staging: row = t>>1, half = t&1 (64B each); 4 CP16 per thread
    const int brow = t >> 1;
    const int bhalf = t & 1;
    const hf* Bsrc = B + (size_t)brow * K + bhalf * 32;
    const uint32_t bsw = ((uint32_t)(brow & 7)) << 4;
    const uint32_t bdst = (uint32_t)A_TILE + (uint32_t)brow * ROWB;

    auto CP_chunk = [&](int s, int k0) {
        const uint32_t st = su + (uint32_t)s * STAGE_B;
        #pragma unroll
        for (int c = 0; c < 2; c++)
            CP16(st + adst + (((uint32_t)(aseg * 32 + c * 16)) ^ asw),
                 Asrc + k0 + c * 8);
        #pragma unroll
        for (int c = 0; c < 4; c++)
            CP16(st + bdst + (((uint32_t)(bhalf * 64 + c * 16)) ^ bsw),
                 Bsrc + k0 + c * 8);
    };

    float acc[2][8][4];
    #pragma unroll
    for (int mt = 0; mt < 2; mt++)
        #pragma unroll
        for (int nt = 0; nt < 8; nt++)
            #pragma unroll
            for (int j = 0; j < 4; j++) acc[mt][nt][j] = 0.f;

    const int nch = K / KC;
    #pragma unroll
    for (int s = 0; s < NSTAGE - 1; s++) {
        CP_chunk(s, s * KC);
        CPCOMMIT();
    }

    const int lrow16 = lane & 15;
    const int cg = (lane >> 4) & 1;

    for (int i = 0; i < nch; i++) {
        CPWAIT(NSTAGE - 2);
        __syncthreads();

        const uint32_t st = su + (uint32_t)(i % NSTAGE) * STAGE_B;

        #pragma unroll
        for (int ks = 0; ks < 4; ks++) {
            const uint32_t cbh = (uint32_t)(ks * 32 + cg * 16);
            uint32_t Af[2][4];
            #pragma unroll
            for (int mt = 0; mt < 2; mt++) {
                const int row = wm * 32 + mt * 16 + lrow16;
                const uint32_t swz = (uint32_t)(row & 7) << 4;
                ldsm_x4(st + (uint32_t)row * ROWB + (cbh ^ swz), Af[mt]);
            }
            #pragma unroll
            for (int q = 0; q < 4; q++) {
                const int row = wn * 64 + q * 16 + lrow16;
                const uint32_t swz = (uint32_t)(row & 7) << 4;
                uint32_t r[4];
                ldsm_x4(st + A_TILE + (uint32_t)row * ROWB + (cbh ^ swz), r);
                uint32_t b0[2] = {r[0], r[2]};
                uint32_t b1[2] = {r[1], r[3]};
                #pragma unroll
                for (int mt = 0; mt < 2; mt++) {
                    mma_f16(acc[mt][2 * q + 0], Af[mt], b0);
                    mma_f16(acc[mt][2 * q + 1], Af[mt], b1);
                }
            }
        }

        if (i + NSTAGE - 1 < nch)
            CP_chunk((i + NSTAGE - 1) % NSTAGE, (i + NSTAGE - 1) * KC);
        CPCOMMIT();
    }

    // ---- epilogue ----
    const int er0 = m0 + wm * 32 + (lane >> 2);
    const int ec0 = c0 + wn * 64 + (lane & 3) * 2;
    #pragma unroll
    for (int mt = 0; mt < 2; mt++) {
        #pragma unroll
        for (int g = 0; g < 2; g++) {
            const int row = er0 + mt * 16 + g * 8;
            #pragma unroll
            for (int nt = 0; nt < 8; nt++) {
                const int col = ec0 + nt * 8;
                float v0 = acc[mt][nt][g * 2 + 0];
                float v1 = acc[mt][nt][g * 2 + 1];
                size_t roff = (size_t)row * Nc + col;
                if (EPI == 2) {
                    float2 r = *reinterpret_cast<const float2*>(RES + roff);
                    *reinterpret_cast<float2*>(Cf + roff) =
                        make_float2(v0 + r.x, v1 + r.y);
                } else {
                    if (EPI == 1) {
                        v0 = 0.5f * v0 * (1.0f + erff(v0 * 0.70710678118654752f));
                        v1 = 0.5f * v1 * (1.0f + erff(v1 * 0.70710678118654752f));
                    }
                    *reinterpret_cast<uint32_t*>(Ch + roff) =
                        h2_bits(__floats2half2_rn(v0, v1));
                }
            }
        }
    }
}

template <int EPI>
__global__ void __launch_bounds__(GTHREADS, 1)
mma_gemm(int N, int K,
         const hf* __restrict__ A, const hf* __restrict__ B,
         const float* __restrict__ RES, float* __restrict__ Cf,
         hf* __restrict__ Ch) {
    const int n0 = blockIdx.x * 256;
    gemm_body<EPI>(N, K, blockIdx.y * 128, n0, A, B + (size_t)n0 * K,
                   RES, Cf, Ch);
}

// Fused QKV
__global__ void __launch_bounds__(GTHREADS, 1)
qkv_gemm(const hf* __restrict__ h,
         const hf* __restrict__ wq, const hf* __restrict__ wk,
         const hf* __restrict__ wv,
         hf* __restrict__ q, hf* __restrict__ k, hf* __restrict__ v) {
    const int n0g = blockIdx.x * 256;
    const int sel = n0g >> 11;
    const int n0 = n0g & 2047;
    const hf* B;
    hf* C;
    if (sel == 0)      { B = wq; C = q; }
    else if (sel == 1) { B = wk; C = k; }
    else               { B = wv; C = v; }
    gemm_body<0>(D_MODEL, D_MODEL, blockIdx.y * 128, n0,
                 h, B + (size_t)n0 * D_MODEL, nullptr, nullptr, C);
}

// ================= FP16 flash attention (256 threads, unchanged core) =======
#define ATT_BUF0 32768
#define ATT_MASK 65536
#define ATT_SMEM_BYTES (65536 + 512)

__device__ __forceinline__ void att_stage(
    char* smem, uint32_t sb, uint32_t bufoff,
    const hf* __restrict__ Kg, const hf* __restrict__ Vg,
    const int* __restrict__ bm, int kv0, int slot, int t) {
    {
        const int row = t >> 2;
        const int dq = (t & 3) * 32;
        const size_t goff = (size_t)(kv0 + row) * D_MODEL + dq;
        const uint32_t rbase = sb + bufoff + (uint32_t)row * 256;
        const uint32_t swr = ((uint32_t)(row & 7)) << 4;
        #pragma unroll
        for (int i = 0; i < 4; i++)
            CP16(rbase + (((uint32_t)(dq * 2 + i * 16)) ^ swr),
                 Kg + goff + i * 8);
    }
    {
        const int kvp = t & 31;
        const int dblk = t >> 5;
        const size_t r0 = (size_t)(kv0 + 2 * kvp) * D_MODEL + dblk * 16;
        const size_t r1 = r0 + D_MODEL;
        uint4 h0a = *reinterpret_cast<const uint4*>(Vg + r0);
        uint4 h0b = *reinterpret_cast<const uint4*>(Vg + r0 + 8);
        uint4 h1a = *reinterpret_cast<const uint4*>(Vg + r1);
        uint4 h1b = *reinterpret_cast<const uint4*>(Vg + r1 + 8);
        uint32_t h0[8] = {h0a.x, h0a.y, h0a.z, h0a.w, h0b.x, h0b.y, h0b.z, h0b.w};
        uint32_t h1[8] = {h1a.x, h1a.y, h1a.z, h1a.w, h1b.x, h1b.y, h1b.z, h1b.w};
        const uint32_t koff = (uint32_t)(kvp * 4);
        #pragma unroll
        for (int dd = 0; dd < 8; dd++) {
            const int d0 = dblk * 16 + dd * 2;
            const uint32_t vb0 = sb + bufoff + 16384 + (uint32_t)d0 * 128 +
                                 (koff ^ ((uint32_t)(d0 & 7) << 4));
            const uint32_t vb1 = sb + bufoff + 16384 + (uint32_t)(d0 + 1) * 128 +
                                 (koff ^ ((uint32_t)((d0 + 1) & 7) << 4));
            asm volatile("st.shared.b32 [%0], %1;" :: "r"(vb0),
                         "r"(__byte_perm(h0[dd], h1[dd], 0x5410)) : "memory");
            asm volatile("st.shared.b32 [%0], %1;" :: "r"(vb1),
                         "r"(__byte_perm(h0[dd], h1[dd], 0x7632)) : "memory");
        }
    }
    if (t < 64)
        reinterpret_cast<int*>(smem + ATT_MASK + slot * 256)[t] = bm[kv0 + t];
}

__global__ void __launch_bounds__(256, 1)
flash_attn_h(const hf* __restrict__ Q, const hf* __restrict__ K,
             const hf* __restrict__ V, const int* __restrict__ mask,
             hf* __restrict__ O) {
    extern __shared__ char smem[];
    const uint32_t sb = smem_to_u32(smem);
    const int t = threadIdx.x, lane = t & 31, w = t >> 5;
    const int qi = gridDim.x - 1 - blockIdx.x;
    const int h = blockIdx.y, b = blockIdx.z;
    const int q0 = qi * 128;
    const size_t base = (size_t)b * SEQ * D_MODEL + (size_t)h * HEAD_DIM;
    const int* bm = mask + b * SEQ;
    const float scale = 0.08838834764831845f;

    {
        const int row = t >> 1, half = t & 1;
        const uint4* gq = reinterpret_cast<const uint4*>(
            Q + base + (size_t)(q0 + row) * D_MODEL + half * 64);
        char* qr = smem + (uint32_t)row * 256;
        const uint32_t swr = ((uint32_t)(row & 7)) << 4;
        #pragma unroll
        for (int i = 0; i < 8; i++)
            *reinterpret_cast<uint4*>(
                qr + (((uint32_t)(half * 128 + i * 16)) ^ swr)) = gq[i];
    }
    att_stage(smem, sb, ATT_BUF0, K + base, V + base, bm, 0, 0, t);
    CPCOMMIT();
    CPWAIT(0);
    __syncthreads();

    uint32_t Aq[8][4];
    {
        const int r = w * 16 + (lane & 15);
        const uint32_t swz = ((uint32_t)(r & 7)) << 4;
        const uint32_t cgo = ((uint32_t)(lane >> 4)) << 4;
        const uint32_t qb = sb + (uint32_t)r * 256;
        #pragma unroll
        for (int ds = 0; ds < 8; ds++)
            ldsm_x4(qb + ((((uint32_t)(ds * 32)) + cgo) ^ swz), Aq[ds]);
    }
    __syncthreads();

    float m1 = -1e30f, l1 = 0.f, m2 = -1e30f, l2 = 0.f;
    float acc[16][4];
    #pragma unroll
    for (int nt = 0; nt < 16; nt++)
        #pragma unroll
        for (int c = 0; c < 4; c++) acc[nt][c] = 0.f;

    const int r1g = q0 + w * 16 + (lane >> 2);
    const int r2g = r1g + 8;
    const int nch = 2 * qi + 2;
    const uint32_t cgo = ((uint32_t)(lane >> 4)) << 4;

    for (int j = 0; j < nch; j++) {
        const int s = j & 1;
        const uint32_t bufo = s ? 0u : (uint32_t)ATT_BUF0;
        const int kv0 = j * 64;

        if (j + 1 < nch) {
            att_stage(smem, sb, s ? (uint32_t)ATT_BUF0 : 0u,
                      K + base, V + base, bm, kv0 + 64, (j + 1) & 1, t);
        }
        CPCOMMIT();

        float sacc[8][4];
        #pragma unroll
        for (int nt = 0; nt < 8; nt++)
            #pragma unroll
            for (int c = 0; c < 4; c++) sacc[nt][c] = 0.f;

        #pragma unroll
        for (int g4 = 0; g4 < 4; g4++) {
            const int kr = g4 * 16 + (lane & 15);
            const uint32_t swz = ((uint32_t)(kr & 7)) << 4;
            const uint32_t kb = sb + bufo + (uint32_t)kr * 256;
            #pragma unroll
            for (int ds = 0; ds < 8; ds++) {
                uint32_t r[4];
                ldsm_x4(kb + ((((uint32_t)(ds * 32)) + cgo) ^ swz), r);
                uint32_t b0[2] = {r[0], r[2]};
                uint32_t b1[2] = {r[1], r[3]};
                mma_f16(sacc[2 * g4 + 0], Aq[ds], b0);
                mma_f16(sacc[2 * g4 + 1], Aq[ds], b1);
            }
        }

        const int* mrow = reinterpret_cast<const int*>(smem + ATT_MASK + s * 256);
        #pragma unroll
        for (int nt = 0; nt < 8; nt++) {
            const int c0 = nt * 8 + (lane & 3) * 2;
            const int k0g = kv0 + c0, k1g = k0g + 1;
            const bool mv0 = mrow[c0] != 0, mv1 = mrow[c0 + 1] != 0;
            float v0 = sacc[nt][0] * scale, v1 = sacc[nt][1] * scale;
            float v2 = sacc[nt][2] * scale, v3 = sacc[nt][3] * scale;
            sacc[nt][0] = (k0g > r1g || !mv0) ? -1e9f : v0;
            sacc[nt][1] = (k1g > r1g || !mv1) ? -1e9f : v1;
            sacc[nt][2] = (k0g > r2g || !mv0) ? -1e9f : v2;
            sacc[nt][3] = (k1g > r2g || !mv1) ? -1e9f : v3;
        }

        float mx1 = -1e30f, mx2 = -1e30f;
        #pragma unroll
        for (int nt = 0; nt < 8; nt++) {
            mx1 = fmaxf(mx1, fmaxf(sacc[nt][0], sacc[nt][1]));
            mx2 = fmaxf(mx2, fmaxf(sacc[nt][2], sacc[nt][3]));
        }
        mx1 = fmaxf(mx1, __shfl_xor_sync(0xFFFFFFFFu, mx1, 1));
        mx1 = fmaxf(mx1, __shfl_xor_sync(0xFFFFFFFFu, mx1, 2));
        mx2 = fmaxf(mx2, __shfl_xor_sync(0xFFFFFFFFu, mx2, 1));
        mx2 = fmaxf(mx2, __shfl_xor_sync(0xFFFFFFFFu, mx2, 2));
        const float m1n = fmaxf(m1, mx1), m2n = fmaxf(m2, mx2);
        const float a1 = __expf(m1 - m1n), a2 = __expf(m2 - m2n);
        float s1 = 0.f, s2 = 0.f;
        #pragma unroll
        for (int nt = 0; nt < 8; nt++) {
            sacc[nt][0] = __expf(sacc[nt][0] - m1n);
            sacc[nt][1] = __expf(sacc[nt][1] - m1n);
            sacc[nt][2] = __expf(sacc[nt][2] - m2n);
            sacc[nt][3] = __expf(sacc[nt][3] - m2n);
            s1 += sacc[nt][0] + sacc[nt][1];
            s2 += sacc[nt][2] + sacc[nt][3];
        }
        s1 += __shfl_xor_sync(0xFFFFFFFFu, s1, 1);
        s1 += __shfl_xor_sync(0xFFFFFFFFu, s1, 2);
        s2 += __shfl_xor_sync(0xFFFFFFFFu, s2, 1);
        s2 += __shfl_xor_sync(0xFFFFFFFFu, s2, 2);
        l1 = l1 * a1 + s1; m1 = m1n;
        l2 = l2 * a2 + s2; m2 = m2n;
        #pragma unroll
        for (int nt = 0; nt < 16; nt++) {
            acc[nt][0] *= a1; acc[nt][1] *= a1;
            acc[nt][2] *= a2; acc[nt][3] *= a2;
        }

        #pragma unroll
        for (int ks = 0; ks < 4; ks++) {
            const float* p0 = sacc[2 * ks];
            const float* p1 = sacc[2 * ks + 1];
            uint32_t pa[4];
            pa[0] = h2_bits(__floats2half2_rn(p0[0], p0[1]));
            pa[1] = h2_bits(__floats2half2_rn(p0[2], p0[3]));
            pa[2] = h2_bits(__floats2half2_rn(p1[0], p1[1]));
            pa[3] = h2_bits(__floats2half2_rn(p1[2], p1[3]));

            #pragma unroll
            for (int gd = 0; gd < 8; gd++) {
                const int dr = gd * 16 + (lane & 15);
                const uint32_t swz = ((uint32_t)(dr & 7)) << 4;
                const uint32_t vb = sb + bufo + 16384 + (uint32_t)dr * 128;
                uint32_t r[4];
                ldsm_x4(vb + ((((uint32_t)(ks * 32)) + cgo) ^ swz), r);
                uint32_t b0[2] = {r[0], r[2]};
                uint32_t b1[2] = {r[1], r[3]};
                mma_f16(acc[2 * gd + 0], pa, b0);
                mma_f16(acc[2 * gd + 1], pa, b1);
            }
        }

        CPWAIT(0);
        __syncthreads();
    }

    const float i1 = (l1 > 0.f) ? 1.f / l1 : 0.f;
    const float i2 = (l2 > 0.f) ? 1.f / l2 : 0.f;
    #pragma unroll
    for (int nt = 0; nt < 16; nt++) {
        const int col = nt * 8 + (lane & 3) * 2;
        *reinterpret_cast<uint32_t*>(O + base + (size_t)r1g * D_MODEL + col) =
            h2_bits(__floats2half2_rn(acc[nt][0] * i1, acc[nt][1] * i1));
        *reinterpret_cast<uint32_t*>(O + base + (size_t)r2g * D_MODEL + col) =
            h2_bits(__floats2half2_rn(acc[nt][2] * i2, acc[nt][3] * i2));
    }
}

// ---------------- launch -----------------------------------------------------
extern "C" void kernel_launch(void* const* d_in, const int* in_sizes, int n_in,
                              void* d_out, int out_size) {
    const float* x           = (const float*)d_in[0];
    const int*   attn_mask   = (const int*)  d_in[1];
    const float* w_norm_attn = (const float*)d_in[2];
    const float* wq          = (const float*)d_in[3];
    const float* wk          = (const float*)d_in[4];
    const float* wv          = (const float*)d_in[5];
    const float* wo          = (const float*)d_in[6];
    const float* w_norm_mlp  = (const float*)d_in[7];
    const float* w_up        = (const float*)d_in[8];
    const float* w_down      = (const float*)d_in[9];
    float* out = (float*)d_out;

    hf *h, *q, *k, *v, *att, *up;
    hf *rwq, *rwk, *rwv, *rwo, *rwu, *rwd;
    float* x1;
    cudaGetSymbolAddress((void**)&h, g_h);
    cudaGetSymbolAddress((void**)&q, g_q);
    cudaGetSymbolAddress((void**)&k, g_k);
    cudaGetSymbolAddress((void**)&v, g_v);
    cudaGetSymbolAddress((void**)&att, g_att);
    cudaGetSymbolAddress((void**)&up, g_up);
    cudaGetSymbolAddress((void**)&x1, g_x1);
    cudaGetSymbolAddress((void**)&rwq, g_wq);
    cudaGetSymbolAddress((void**)&rwk, g_wk);
    cudaGetSymbolAddress((void**)&rwv, g_wv);
    cudaGetSymbolAddress((void**)&rwo, g_wo);
    cudaGetSymbolAddress((void**)&rwu, g_wu);
    cudaGetSymbolAddress((void**)&rwd, g_wd);

    cudaFuncSetAttribute(flash_attn_h,
                         cudaFuncAttributeMaxDynamicSharedMemorySize, ATT_SMEM_BYTES);
    cudaFuncSetAttribute(qkv_gemm,
                         cudaFuncAttributeMaxDynamicSharedMemorySize, GEMM_SMEM);
    cudaFuncSetAttribute(mma_gemm<1>,
                         cudaFuncAttributeMaxDynamicSharedMemorySize, GEMM_SMEM);
    cudaFuncSetAttribute(mma_gemm<2>,
                         cudaFuncAttributeMaxDynamicSharedMemorySize, GEMM_SMEM);

    // 0) round weights to fp16 (once)
    const int DD4 = D_MODEL * D_MODEL / 4;
    const int UD4 = MLP_DIM * D_MODEL / 4;
    round_dd<<<dim3((DD4 + 255) / 256, 4), 256>>>(wq, wk, wv, wo,
                                                  rwq, rwk, rwv, rwo);
    round_ud<<<dim3((UD4 + 255) / 256, 2), 256>>>(w_up, w_down, rwu, rwd);

    // 1) rmsnorm(x) -> h (fp16)
    rmsnorm_h<<<TOK, 256>>>(x, w_norm_attn, h);

    // 2) fused q,k,v projection  [launch #4]
    dim3 gQKV(3 * D_MODEL / 256, TOK / 128);
    qkv_gemm<<<gQKV, GTHREADS, GEMM_SMEM>>>(h, rwq, rwk, rwv, q, k, v);

    // 3) attention
    dim3 gA(SEQ / 128, N_HEADS, BATCH);
    flash_attn_h<<<gA, 256, ATT_SMEM_BYTES>>>(q, k, v, attn_mask, att);

    // 4) output projection + residual -> x1 (fp32)   [launch #6: profiled]
    dim3 gD(D_MODEL / 256, TOK / 128);
    mma_gemm<2><<<gD, GTHREADS, GEMM_SMEM>>>(D_MODEL, D_MODEL,
                                             att, rwo, x, x1, nullptr);

    // 5) rmsnorm(x1) -> h
    rmsnorm_h<<<TOK, 256>>>(x1, w_norm_mlp, h);

    // 6) up projection + gelu (fp16 store)
    dim3 gU(MLP_DIM / 256, TOK / 128);
    mma_gemm<1><<<gU, GTHREADS, GEMM_SMEM>>>(MLP_DIM, D_MODEL,
                                             h, rwu, nullptr, nullptr, up);

    // 7) down projection + residual -> out (fp32)
    mma_gemm<2><<<gD, GTHREADS, GEMM_SMEM>>>(D_MODEL, MLP_DIM,
                                             up, rwd, x1, out, nullptr);
}